// round 9
// baseline (speedup 1.0000x reference)
#include <cuda_runtime.h>

// ---------------------------------------------------------------------------
// Problem constants
// ---------------------------------------------------------------------------
constexpr int Bn  = 8;
constexpr int CH  = 128;
constexpr int H   = 80;
constexpr int W   = 80;
constexpr int HW  = H * W;
constexpr int MID = 16;
constexpr int KD  = CH * 9;          // 1152
constexpr int TPB = 320;             // 16 co-groups x 20 px-groups (4 px each)
constexpr float EPS = 1e-5f;

// ---------------------------------------------------------------------------
// Scratch
// ---------------------------------------------------------------------------
__device__ float g_h[Bn * CH * HW];
__device__ float g_off[Bn * 27 * HW];
__device__ float g_vals[(size_t)Bn * CH * 9 * HW];   // [b][c*9+k][y][x]
__device__ float g_iral[Bn * CH * HW];
__device__ float g_g1[Bn * MID * HW];
__device__ float g_gate[Bn * HW];
__device__ float g_fin[Bn * 2 * CH * HW];            // fused conv input concat
// transposed weights [k][co] (row-major, contiguous in co) for cp16 staging
__device__ float g_w0t[2 * CH * 9 * CH];             // 2304 x 128
__device__ float g_wft[2 * CH * 9 * CH];             // 2304 x 128
__device__ float g_wdt[KD * CH];                     // 1152 x 128
__device__ float g_w2t[KD * 32];                     // 1152 x 32 (27 zero-padded)

#define DEV __device__ __forceinline__
typedef unsigned long long ull;
typedef unsigned int u32;

DEV float sigm_(float x) { return 1.0f / (1.0f + __expf(-x)); }
DEV float silu_(float x) { return x * sigm_(x); }

DEV void ffma2(ull& d, ull a, ull b) {
    asm("fma.rn.f32x2 %0, %1, %2, %0;" : "+l"(d) : "l"(a), "l"(b));
}
DEV ull dup2(float w) { ull u; asm("mov.b64 %0, {%1, %1};" : "=l"(u) : "f"(w)); return u; }
DEV void unpack2(ull u, float& x, float& y) {
    asm("mov.b64 {%0, %1}, %2;" : "=f"(x), "=f"(y) : "l"(u));
}
DEV u32 smem_u32(const void* p) {
    u32 a; asm("{ .reg .u64 t; cvta.to.shared.u64 t, %1; cvt.u32.u64 %0, t; }" : "=r"(a) : "l"(p));
    return a;
}
DEV void cp4(u32 dst, const float* src) {
    asm volatile("cp.async.ca.shared.global [%0], [%1], 4;" :: "r"(dst), "l"(src) : "memory");
}
DEV void cp16(u32 dst, const float* src) {
    asm volatile("cp.async.cg.shared.global [%0], [%1], 16;" :: "r"(dst), "l"(src) : "memory");
}
DEV void cp4z(u32 dst, const float* src, bool ok) {
    int sz = ok ? 4 : 0;
    asm volatile("cp.async.ca.shared.global [%0], [%1], 4, %2;"
                 :: "r"(dst), "l"(src), "r"(sz) : "memory");
}
DEV void cp_commit() { asm volatile("cp.async.commit_group;" ::: "memory"); }
DEV void cp_wait1()  { asm volatile("cp.async.wait_group 1;" ::: "memory"); }
DEV void cp_wait0()  { asm volatile("cp.async.wait_group 0;" ::: "memory"); }

// ---------------------------------------------------------------------------
// Weight transpose prep: src [co][K] -> dst [K][cols] (cols >= cout, padded 0)
// ---------------------------------------------------------------------------
__global__ __launch_bounds__(256)
void prep_w_kernel(const float* __restrict__ src, float* __restrict__ dst,
                   int K, int cols, int cout) {
    int idx = blockIdx.x * 256 + threadIdx.x;
    if (idx >= K * cols) return;
    int r = idx / cols, co = idx % cols;
    dst[idx] = (co < cout) ? src[(size_t)co * K + r] : 0.0f;
}

// ---------------------------------------------------------------------------
// 3x3 tiled conv, cp.async double-buffered, transposed-weight cp16 staging.
//   MODE 0: concat(rgb, ir)  Cin=256 -> g_h   (silu(v+b))
//   MODE 1: g_fin            Cin=256 -> out   (silu(bn)+res)
//   MODE 3: g_h              Cin=128 -> g_off (v+b)
// Block: 320 thr = 16 co-groups x 20 px-groups (4 px), 2 output rows.
// ---------------------------------------------------------------------------
template <int MODE>
__global__ __launch_bounds__(TPB, 2)
void conv_kernel(const float* __restrict__ A, const float* __restrict__ Bp,
                 const float* __restrict__ wT,
                 const float* __restrict__ bias_or_bn,
                 const float* __restrict__ res_scale,
                 float* __restrict__ out_param) {
    constexpr int KS2  = 9;
    constexpr int CIN  = (MODE == 3) ? CH : 2 * CH;
    constexpr int COUT = (MODE == 3) ? 27 : CH;
    constexpr int RCO  = (MODE == 3) ? 2 : 4;
    constexpr int CO_TILE = 16 * RCO;
    constexpr int CO_PAD  = CO_TILE + 4;
    constexpr int WCOLS = (MODE == 3) ? 32 : 128;
    constexpr int CC   = 8;
    constexpr int S    = CC * KS2;                  // 72
    constexpr int XW   = W + 2;
    constexpr int SM_WF = S * CO_PAD;               // floats per weight buffer
    constexpr int SM_IF = CC * 3 * XW;              // float2 per input buffer
    constexpr int NCK  = CIN / CC;
    constexpr int NW16 = S * (CO_TILE / 4);         // cp16 ops per weight stage

    extern __shared__ float sm[];
    float*  sW = sm;                               // [2][SM_WF]
    float2* sI = (float2*)(sm + 2 * SM_WF);        // [2][SM_IF]

    const int tid = threadIdx.x;
    const int tco = tid & 15;
    const int tpx = tid >> 4;          // 0..19
    const int x0  = tpx * 4;
    const int b   = blockIdx.x / (H / 2);
    const int y0  = (blockIdx.x % (H / 2)) * 2;
    const int co_base = blockIdx.y * CO_TILE;

    const u32 swb = smem_u32(sW);
    const u32 sib = smem_u32(sI);

    ull acc[RCO][4];
#pragma unroll
    for (int r = 0; r < RCO; r++)
#pragma unroll
        for (int p = 0; p < 4; p++) acc[r][p] = 0ull;

    auto chan_ptr = [&](int ci) -> const float* {
        if (MODE == 0) return (ci < CH) ? A + (size_t)(b * CH + ci) * HW
                                        : Bp + (size_t)(b * CH + (ci - CH)) * HW;
        else if (MODE == 1) return g_fin + (size_t)(b * 2 * CH + ci) * HW;
        else return g_h + (size_t)(b * CH + ci) * HW;
    };

    auto stage = [&](int ck, int buf) {
        const int ci0 = ck * CC;
        const float* wsrc = wT + (size_t)(ci0 * 9) * WCOLS + co_base;
        for (int idx = tid; idx < NW16; idx += TPB) {
            int s = idx / (CO_TILE / 4), j = idx % (CO_TILE / 4);
            cp16(swb + (u32)(buf * SM_WF + s * CO_PAD + j * 4) * 4u,
                 wsrc + (size_t)s * WCOLS + j * 4);
        }
        for (int idx = tid; idx < CC * 3 * XW; idx += TPB) {
            int ci  = idx / (3 * XW);
            int rem = idx % (3 * XW);
            int ry  = rem / XW;
            int xx  = rem % XW;
            int gx  = xx - 1;
            int gy0 = y0 - 1 + ry;
            int gy1 = gy0 + 1;
            bool okx = (gx >= 0) && (gx < W);
            const float* src = chan_ptr(ci0 + ci) + gy0 * W + gx;
            u32 dst = sib + (u32)(buf * SM_IF + (ci * 3 + ry) * XW + xx) * 8u;
            cp4z(dst,     src,     okx && (gy0 >= 0) && (gy0 < H));
            cp4z(dst + 4, src + W, okx && (gy1 < H));
        }
        cp_commit();
    };

    stage(0, 0);

    for (int ck = 0; ck < NCK; ck++) {
        const int buf = ck & 1;
        if (ck + 1 < NCK) { stage(ck + 1, buf ^ 1); cp_wait1(); }
        else              { cp_wait0(); }
        __syncthreads();

        const float*  wbuf = sW + buf * SM_WF;
        const float2* ibuf = sI + buf * SM_IF;
        for (int ci = 0; ci < CC; ++ci) {
#pragma unroll
            for (int ky = 0; ky < 3; ky++) {
                const ull* ip = reinterpret_cast<const ull*>(&ibuf[(ci * 3 + ky) * XW + x0]);
                ull vv[6];
#pragma unroll
                for (int j = 0; j < 6; j++) vv[j] = ip[j];
#pragma unroll
                for (int kx = 0; kx < 3; kx++) {
                    const int s = ci * KS2 + ky * 3 + kx;
                    const float* wp = &wbuf[s * CO_PAD + tco * RCO];
                    ull w2[RCO];
                    if (RCO == 4) {
                        float4 w4 = *reinterpret_cast<const float4*>(wp);
                        w2[0] = dup2(w4.x); w2[1] = dup2(w4.y);
                        w2[2] = dup2(w4.z); w2[3] = dup2(w4.w);
                    } else {
                        float2 wv = *reinterpret_cast<const float2*>(wp);
                        w2[0] = dup2(wv.x); w2[1] = dup2(wv.y);
                    }
#pragma unroll
                    for (int p = 0; p < 4; p++)
#pragma unroll
                        for (int r = 0; r < RCO; r++) ffma2(acc[r][p], w2[r], vv[kx + p]);
                }
            }
        }
        __syncthreads();
    }

    float* optr = (MODE == 0) ? g_h : (MODE == 3) ? g_off : out_param;
#pragma unroll
    for (int r = 0; r < RCO; r++) {
        int co = co_base + tco * RCO + r;
        if (co >= COUT) continue;
        float bnb, bns = 1.0f, rs = 0.0f;
        if (MODE == 1) {
            float gm = bias_or_bn[co];
            float bt = bias_or_bn[COUT + co];
            float mn = bias_or_bn[2 * COUT + co];
            float vr = bias_or_bn[3 * COUT + co];
            bns = gm * rsqrtf(vr + EPS);
            bnb = bt - mn * bns;
            rs  = *res_scale;
        } else {
            bnb = bias_or_bn[co];
        }
#pragma unroll
        for (int p = 0; p < 4; p++) {
            int x = x0 + p;
            int o0 = ((b * COUT + co) * H + y0) * W + x;
            int o1 = o0 + W;
            float a0, a1;
            unpack2(acc[r][p], a0, a1);
            if (MODE == 0) {
                optr[o0] = silu_(a0 + bnb);
                optr[o1] = silu_(a1 + bnb);
            } else if (MODE == 1) {
                optr[o0] = silu_(a0 * bns + bnb) + rs * g_iral[o0];
                optr[o1] = silu_(a1 * bns + bnb) + rs * g_iral[o1];
            } else {
                optr[o0] = a0 + bnb;
                optr[o1] = a1 + bnb;
            }
        }
    }
}

// ---------------------------------------------------------------------------
// DCN 1x1 conv (Cin=1152 -> 128), cp.async double-buffered, cp16 weights.
// Block: 320 thr = 16 co-groups x 20 px-groups (4 px), 2 rows.
// ---------------------------------------------------------------------------
constexpr int DCC     = 32;
constexpr int DCO_T   = 64;
constexpr int DCO_PAD = 68;
constexpr int DIELEM  = DCC * W;
constexpr int DSM_W   = DCC * DCO_PAD;
constexpr int DSM_I   = DCC * W;
constexpr int DCN_SMEM = (2 * DSM_W) * 4 + (2 * DSM_I) * 8;

__global__ __launch_bounds__(TPB, 2)
void dcn_conv_kernel(const float* __restrict__ bias) {
    extern __shared__ float dsm[];
    float*  sW = dsm;
    float2* sI = (float2*)(dsm + 2 * DSM_W);

    const int tid = threadIdx.x;
    const int tco = tid & 15;
    const int tpx = tid >> 4;          // 0..19
    const int x0  = tpx * 4;
    const int b   = blockIdx.x / (H / 2);
    const int y0  = (blockIdx.x % (H / 2)) * 2;
    const int co_base = blockIdx.y * DCO_T;

    const u32 swb = smem_u32(sW);
    const u32 sib = smem_u32(sI);
    const float* vbase = g_vals + (size_t)b * KD * HW + (size_t)y0 * W;

    ull acc[4][4];
#pragma unroll
    for (int r = 0; r < 4; r++)
#pragma unroll
        for (int p = 0; p < 4; p++) acc[r][p] = 0ull;

    auto stage = [&](int ck, int buf) {
        const int ci0 = ck * DCC;
        const float* wsrc = g_wdt + (size_t)ci0 * CH + co_base;
        for (int idx = tid; idx < DCC * 16; idx += TPB) {
            int s = idx >> 4, j = idx & 15;
            cp16(swb + (u32)(buf * DSM_W + s * DCO_PAD + j * 4) * 4u,
                 wsrc + (size_t)s * CH + j * 4);
        }
#pragma unroll
        for (int i = 0; i < DIELEM / TPB; i++) {
            int idx = i * TPB + tid;
            int ci = idx / W, xx = idx % W;
            const float* src = vbase + (size_t)(ci0 + ci) * HW + xx;
            u32 dst = sib + (u32)(buf * DSM_I + ci * W + xx) * 8u;
            cp4(dst, src);
            cp4(dst + 4, src + W);
        }
        cp_commit();
    };

    stage(0, 0);

    constexpr int NCK = KD / DCC;
    for (int ck = 0; ck < NCK; ck++) {
        const int buf = ck & 1;
        if (ck + 1 < NCK) { stage(ck + 1, buf ^ 1); cp_wait1(); }
        else              { cp_wait0(); }
        __syncthreads();

        const float*  wbuf = sW + buf * DSM_W;
        const float2* ibuf = sI + buf * DSM_I;
#pragma unroll 4
        for (int ci = 0; ci < DCC; ++ci) {
            const ull* ip = reinterpret_cast<const ull*>(&ibuf[ci * W + x0]);
            ull vv[4];
#pragma unroll
            for (int p = 0; p < 4; p++) vv[p] = ip[p];
            float4 w4 = *reinterpret_cast<const float4*>(&wbuf[ci * DCO_PAD + tco * 4]);
            ull w2[4] = { dup2(w4.x), dup2(w4.y), dup2(w4.z), dup2(w4.w) };
#pragma unroll
            for (int p = 0; p < 4; p++)
#pragma unroll
                for (int r = 0; r < 4; r++) ffma2(acc[r][p], w2[r], vv[p]);
        }
        __syncthreads();
    }

#pragma unroll
    for (int r = 0; r < 4; r++) {
        int co = co_base + tco * 4 + r;
        float bs = __ldg(&bias[co]);
#pragma unroll
        for (int p = 0; p < 4; p++) {
            int x = x0 + p;
            int o0 = ((b * CH + co) * H + y0) * W + x;
            float a0, a1;
            unpack2(acc[r][p], a0, a1);
            g_iral[o0]     = a0 + bs;
            g_iral[o0 + W] = a1 + bs;
        }
    }
}

// ---------------------------------------------------------------------------
// Deformable bilinear sampling -> g_vals[b][c*9+k][y][x]
// ---------------------------------------------------------------------------
__global__ __launch_bounds__(256)
void deform_kernel(const float* __restrict__ ir) {
    const int blk   = blockIdx.x;
    const int ytile = blk % 27;
    const int bk    = blk / 27;
    const int k     = bk % 9;
    const int b     = bk / 9;
    const int tid   = threadIdx.x;
    if (tid >= 240) return;
    const int y = ytile * 3 + tid / 80;
    const int x = tid % 80;
    if (y >= H) return;

    const float* obase = g_off + (b * 27) * HW + y * W + x;
    float oy = obase[(2 * k) * HW];
    float ox = obase[(2 * k + 1) * HW];
    float m  = sigm_(obase[(18 + k) * HW]);

    const int ky = k / 3 - 1;
    const int kx = k % 3 - 1;
    float ys = oy + (float)(ky + y);
    float xs = ox + (float)(kx + x);
    float fy = floorf(ys), fx = floorf(xs);
    float wy = ys - fy,    wx = xs - fx;
    int y0 = (int)fy, x0 = (int)fx;
    int y1 = y0 + 1,  x1 = x0 + 1;
    bool vy0 = (y0 >= 0) && (y0 < H);
    bool vy1 = (y1 >= 0) && (y1 < H);
    bool vx0 = (x0 >= 0) && (x0 < W);
    bool vx1 = (x1 >= 0) && (x1 < W);
    float w00 = (1.0f - wy) * (1.0f - wx) * m * ((vy0 && vx0) ? 1.0f : 0.0f);
    float w01 = (1.0f - wy) * wx          * m * ((vy0 && vx1) ? 1.0f : 0.0f);
    float w10 = wy          * (1.0f - wx) * m * ((vy1 && vx0) ? 1.0f : 0.0f);
    float w11 = wy          * wx          * m * ((vy1 && vx1) ? 1.0f : 0.0f);
    int cy0 = min(max(y0, 0), H - 1), cy1 = min(max(y1, 0), H - 1);
    int cx0 = min(max(x0, 0), W - 1), cx1 = min(max(x1, 0), W - 1);
    int i00 = cy0 * W + cx0, i01 = cy0 * W + cx1;
    int i10 = cy1 * W + cx0, i11 = cy1 * W + cx1;

    const float* ib = ir + b * CH * HW;
    float* vout = g_vals + ((size_t)b * CH * 9 + k) * HW + y * W + x;
#pragma unroll 4
    for (int c = 0; c < CH; c++) {
        const float* p = ib + c * HW;
        float v = w00 * __ldg(p + i00) + w01 * __ldg(p + i01)
                + w10 * __ldg(p + i10) + w11 * __ldg(p + i11);
        vout[(size_t)c * 9 * HW] = v;
    }
}

// ---------------------------------------------------------------------------
// Gate stage 1: 1x1 conv 256 -> 16 + BN + SiLU -> g_g1
// ---------------------------------------------------------------------------
__global__ __launch_bounds__(256)
void gate1_kernel(const float* __restrict__ rgb,
                  const float* __restrict__ wg1,
                  const float* __restrict__ bng1) {
    __shared__ float sg[2 * CH * MID];
    const int tid = threadIdx.x;
    for (int i = tid; i < 2 * CH * MID; i += 256) {
        int ci = i >> 4, o = i & 15;
        sg[i] = wg1[o * (2 * CH) + ci];
    }
    __syncthreads();
    const int idx = blockIdx.x * 256 + tid;
    if (idx >= Bn * HW) return;
    const int b = idx / HW, p = idx % HW;

    float acc[MID];
#pragma unroll
    for (int o = 0; o < MID; o++) acc[o] = 0.0f;

    const float* rp = rgb    + b * CH * HW + p;
    const float* ip = g_iral + b * CH * HW + p;
    for (int ci = 0; ci < CH; ci++) {
        float v = rp[ci * HW];
        const float* w = &sg[ci * MID];
#pragma unroll
        for (int o = 0; o < MID; o++) acc[o] += w[o] * v;
    }
    for (int ci = 0; ci < CH; ci++) {
        float v = ip[ci * HW];
        const float* w = &sg[(CH + ci) * MID];
#pragma unroll
        for (int o = 0; o < MID; o++) acc[o] += w[o] * v;
    }
#pragma unroll
    for (int o = 0; o < MID; o++) {
        float gm = bng1[o], bt = bng1[MID + o];
        float mn = bng1[2 * MID + o], vr = bng1[3 * MID + o];
        float sc = gm * rsqrtf(vr + EPS);
        g_g1[(b * MID + o) * HW + p] = silu_(acc[o] * sc + bt - mn * sc);
    }
}

// ---------------------------------------------------------------------------
// Gate stages 2+3, then materialize fused conv input g_fin
// ---------------------------------------------------------------------------
__global__ __launch_bounds__(256)
void gate23_kernel(const float* __restrict__ wg2,
                   const float* __restrict__ bng2,
                   const float* __restrict__ wg3,
                   const float* __restrict__ bg3,
                   const float* __restrict__ rgb) {
    const int idx = blockIdx.x * 256 + threadIdx.x;
    if (idx >= Bn * HW) return;
    const int b = idx / HW, p = idx % HW;
    const int y = p / W, x = p % W;

    float s3 = __ldg(bg3);
#pragma unroll
    for (int o = 0; o < MID; o++) {
        const float* gp = g_g1 + (b * MID + o) * HW;
        float s = 0.0f;
#pragma unroll
        for (int ky = 0; ky < 3; ky++) {
            int yy = y + ky - 1;
            if (yy < 0 || yy >= H) continue;
#pragma unroll
            for (int kx = 0; kx < 3; kx++) {
                int xx = x + kx - 1;
                if (xx < 0 || xx >= W) continue;
                s += gp[yy * W + xx] * __ldg(&wg2[o * 9 + ky * 3 + kx]);
            }
        }
        float gm = __ldg(&bng2[o]), bt = __ldg(&bng2[MID + o]);
        float mn = __ldg(&bng2[2 * MID + o]), vr = __ldg(&bng2[3 * MID + o]);
        float sc = gm * rsqrtf(vr + EPS);
        s3 += silu_(s * sc + bt - mn * sc) * __ldg(&wg3[o]);
    }
    float gv = sigm_(s3);
    g_gate[b * HW + p] = gv;

    const float* ip = g_iral + (size_t)b * CH * HW + p;
    const float* rp = rgb    + (size_t)b * CH * HW + p;
    float* f0 = g_fin + (size_t)b * 2 * CH * HW + p;
    float* f1 = f0 + (size_t)CH * HW;
    float om = 1.0f - gv;
#pragma unroll 4
    for (int c = 0; c < CH; c++) {
        f0[(size_t)c * HW] = gv * ip[(size_t)c * HW];
        f1[(size_t)c * HW] = om * rp[(size_t)c * HW];
    }
}

// ---------------------------------------------------------------------------
// Launcher
// ---------------------------------------------------------------------------
extern "C" void kernel_launch(void* const* d_in, const int* in_sizes, int n_in,
                              void* d_out, int out_size) {
    const float* rgb    = (const float*)d_in[0];
    const float* ir     = (const float*)d_in[1];
    const float* w_off1 = (const float*)d_in[2];
    const float* b_off1 = (const float*)d_in[3];
    const float* w_off2 = (const float*)d_in[4];
    const float* b_off2 = (const float*)d_in[5];
    const float* w_dcn  = (const float*)d_in[6];
    const float* b_dcn  = (const float*)d_in[7];
    const float* w_g1   = (const float*)d_in[8];
    const float* bn_g1  = (const float*)d_in[9];
    const float* w_g2   = (const float*)d_in[10];
    const float* bn_g2  = (const float*)d_in[11];
    const float* w_g3   = (const float*)d_in[12];
    const float* b_g3   = (const float*)d_in[13];
    const float* w_f    = (const float*)d_in[14];
    const float* bn_f   = (const float*)d_in[15];
    const float* rscale = (const float*)d_in[16];
    float* out = (float*)d_out;

    float* w0t; cudaGetSymbolAddress((void**)&w0t, g_w0t);
    float* wft; cudaGetSymbolAddress((void**)&wft, g_wft);
    float* wdt; cudaGetSymbolAddress((void**)&wdt, g_wdt);
    float* w2t; cudaGetSymbolAddress((void**)&w2t, g_w2t);

    // double-buffered smem sizes (identical layout to R8)
    const int sm_big = 2 * ((72 * 68) * 4 + (8 * 3 * 82) * 8);   // 70656 B
    const int sm_off = 2 * ((72 * 36) * 4 + (8 * 3 * 82) * 8);   // 52224 B

    cudaFuncSetAttribute(conv_kernel<0>, cudaFuncAttributeMaxDynamicSharedMemorySize, sm_big);
    cudaFuncSetAttribute(conv_kernel<1>, cudaFuncAttributeMaxDynamicSharedMemorySize, sm_big);
    cudaFuncSetAttribute(conv_kernel<3>, cudaFuncAttributeMaxDynamicSharedMemorySize, sm_off);
    cudaFuncSetAttribute(dcn_conv_kernel, cudaFuncAttributeMaxDynamicSharedMemorySize, DCN_SMEM);

    const int BX = Bn * (H / 2);   // 320 row-pair blocks

    // 0) weight transposes
    prep_w_kernel<<<(2304 * 128 + 255) / 256, 256>>>(w_off1, w0t, 2304, 128, 128);
    prep_w_kernel<<<(2304 * 128 + 255) / 256, 256>>>(w_f,    wft, 2304, 128, 128);
    prep_w_kernel<<<(1152 * 128 + 255) / 256, 256>>>(w_dcn,  wdt, 1152, 128, 128);
    prep_w_kernel<<<(1152 * 32 + 255) / 256, 256>>>(w_off2,  w2t, 1152, 32, 27);

    // 1) h = silu(conv3x3(concat(rgb, ir)))
    conv_kernel<0><<<dim3(BX, 2), TPB, sm_big>>>(rgb, ir, w0t, b_off1, nullptr, nullptr);
    // 2) offset/mask conv (27 ch)
    conv_kernel<3><<<dim3(BX, 1), TPB, sm_off>>>(nullptr, nullptr, w2t, b_off2, nullptr, nullptr);
    // 3) deformable bilinear sampling * mask -> g_vals
    deform_kernel<<<Bn * 9 * 27, 256>>>(ir);
    // 4) ir_aligned = vals . w_dcn + b_dcn
    dcn_conv_kernel<<<dim3(BX, 2), TPB, DCN_SMEM>>>(b_dcn);
    // 5) gate stage 1
    gate1_kernel<<<(Bn * HW + 255) / 256, 256>>>(rgb, w_g1, bn_g1);
    // 6) gate stages 2+3 + fused-input materialization
    gate23_kernel<<<(Bn * HW + 255) / 256, 256>>>(w_g2, bn_g2, w_g3, b_g3, rgb);
    // 7) fused conv + BN + SiLU + residual -> out
    conv_kernel<1><<<dim3(BX, 2), TPB, sm_big>>>(nullptr, nullptr, wft, bn_f, rscale, out);
}

// round 10
// speedup vs baseline: 1.7279x; 1.7279x over previous
#include <cuda_runtime.h>

// ---------------------------------------------------------------------------
// Problem constants
// ---------------------------------------------------------------------------
constexpr int Bn  = 8;
constexpr int CH  = 128;
constexpr int H   = 80;
constexpr int W   = 80;
constexpr int HW  = H * W;
constexpr int MID = 16;
constexpr int KD  = CH * 9;          // 1152
constexpr float EPS = 1e-5f;

// ---------------------------------------------------------------------------
// Scratch
// ---------------------------------------------------------------------------
__device__ float g_h[Bn * CH * HW];
__device__ float g_off[Bn * 27 * HW];
__device__ float g_vals[(size_t)Bn * CH * 9 * HW];   // [b][c*9+k][y][x]
__device__ float g_iral[Bn * CH * HW];
__device__ float g_g1[Bn * MID * HW];
__device__ float g_gate[Bn * HW];
__device__ float g_fin[Bn * 2 * CH * HW];            // fused conv input concat
// transposed weights [k][co] (row-major, contiguous in co) for cp16 staging
__device__ float g_w0t[2 * CH * 9 * CH];             // 2304 x 128
__device__ float g_wft[2 * CH * 9 * CH];             // 2304 x 128
__device__ float g_wdt[KD * CH];                     // 1152 x 128
__device__ float g_w2t[KD * 32];                     // 1152 x 32 (27 zero-padded)

#define DEV __device__ __forceinline__
typedef unsigned long long ull;
typedef unsigned int u32;

DEV float sigm_(float x) { return 1.0f / (1.0f + __expf(-x)); }
DEV float silu_(float x) { return x * sigm_(x); }

DEV void ffma2(ull& d, ull a, ull b) {
    asm("fma.rn.f32x2 %0, %1, %2, %0;" : "+l"(d) : "l"(a), "l"(b));
}
DEV ull dup2(float w) { ull u; asm("mov.b64 %0, {%1, %1};" : "=l"(u) : "f"(w)); return u; }
DEV void unpack2(ull u, float& x, float& y) {
    asm("mov.b64 {%0, %1}, %2;" : "=f"(x), "=f"(y) : "l"(u));
}
DEV u32 smem_u32(const void* p) {
    u32 a; asm("{ .reg .u64 t; cvta.to.shared.u64 t, %1; cvt.u32.u64 %0, t; }" : "=r"(a) : "l"(p));
    return a;
}
DEV void cp4(u32 dst, const float* src) {
    asm volatile("cp.async.ca.shared.global [%0], [%1], 4;" :: "r"(dst), "l"(src) : "memory");
}
DEV void cp16(u32 dst, const float* src) {
    asm volatile("cp.async.cg.shared.global [%0], [%1], 16;" :: "r"(dst), "l"(src) : "memory");
}
DEV void cp4z(u32 dst, const float* src, bool ok) {
    int sz = ok ? 4 : 0;
    asm volatile("cp.async.ca.shared.global [%0], [%1], 4, %2;"
                 :: "r"(dst), "l"(src), "r"(sz) : "memory");
}
DEV void cp_commit() { asm volatile("cp.async.commit_group;" ::: "memory"); }
DEV void cp_wait2()  { asm volatile("cp.async.wait_group 2;" ::: "memory"); }
DEV void cp_wait1()  { asm volatile("cp.async.wait_group 1;" ::: "memory"); }
DEV void cp_wait0()  { asm volatile("cp.async.wait_group 0;" ::: "memory"); }

// ---------------------------------------------------------------------------
// Weight transpose prep: src [co][K] -> dst [K][cols] (cols >= cout, padded 0)
// ---------------------------------------------------------------------------
__global__ __launch_bounds__(256)
void prep_w_kernel(const float* __restrict__ src, float* __restrict__ dst,
                   int K, int cols, int cout) {
    int idx = blockIdx.x * 256 + threadIdx.x;
    if (idx >= K * cols) return;
    int r = idx / cols, co = idx % cols;
    dst[idx] = (co < cout) ? src[(size_t)co * K + r] : 0.0f;
}

// ---------------------------------------------------------------------------
// 3x3 tiled conv, cp.async TRIPLE-buffered, transposed-weight cp16 staging.
//   MODE 0: concat(rgb, ir)  Cin=256 -> g_h   (silu(v+b))
//   MODE 1: g_fin            Cin=256 -> out   (silu(bn)+res)
//   MODE 3: g_h              Cin=128 -> g_off (v+b)
// Block: 256 thr = 16 co-groups x 16 px-groups (5 px), 2 output rows.
// ---------------------------------------------------------------------------
template <int MODE>
__global__ __launch_bounds__(256)
void conv_kernel(const float* __restrict__ A, const float* __restrict__ Bp,
                 const float* __restrict__ wT,
                 const float* __restrict__ bias_or_bn,
                 const float* __restrict__ res_scale,
                 float* __restrict__ out_param) {
    constexpr int KS2  = 9;
    constexpr int CIN  = (MODE == 3) ? CH : 2 * CH;
    constexpr int COUT = (MODE == 3) ? 27 : CH;
    constexpr int RCO  = (MODE == 3) ? 2 : 4;
    constexpr int CO_TILE = 16 * RCO;
    constexpr int CO_PAD  = CO_TILE + 4;
    constexpr int WCOLS = (MODE == 3) ? 32 : 128;
    constexpr int CC   = 8;
    constexpr int S    = CC * KS2;                  // 72
    constexpr int XW   = W + 2;
    constexpr int SM_WF = S * CO_PAD;               // floats per weight buffer
    constexpr int SM_IF = CC * 3 * XW;              // float2 per input buffer
    constexpr int NCK  = CIN / CC;
    constexpr int NW16 = S * (CO_TILE / 4);

    extern __shared__ float sm[];
    float*  sW = sm;                               // [3][SM_WF]
    float2* sI = (float2*)(sm + 3 * SM_WF);        // [3][SM_IF]

    const int tid = threadIdx.x;
    const int tco = tid & 15;
    const int tpx = tid >> 4;
    const int x0  = tpx * 5;
    const int b   = blockIdx.x / (H / 2);
    const int y0  = (blockIdx.x % (H / 2)) * 2;
    const int co_base = blockIdx.y * CO_TILE;

    const u32 swb = smem_u32(sW);
    const u32 sib = smem_u32(sI);

    ull acc[RCO][5];
#pragma unroll
    for (int r = 0; r < RCO; r++)
#pragma unroll
        for (int p = 0; p < 5; p++) acc[r][p] = 0ull;

    auto chan_ptr = [&](int ci) -> const float* {
        if (MODE == 0) return (ci < CH) ? A + (size_t)(b * CH + ci) * HW
                                        : Bp + (size_t)(b * CH + (ci - CH)) * HW;
        else if (MODE == 1) return g_fin + (size_t)(b * 2 * CH + ci) * HW;
        else return g_h + (size_t)(b * CH + ci) * HW;
    };

    auto stage = [&](int ck, int buf) {
        const int ci0 = ck * CC;
        const float* wsrc = wT + (size_t)(ci0 * 9) * WCOLS + co_base;
        for (int idx = tid; idx < NW16; idx += 256) {
            int s = idx / (CO_TILE / 4), j = idx % (CO_TILE / 4);
            cp16(swb + (u32)(buf * SM_WF + s * CO_PAD + j * 4) * 4u,
                 wsrc + (size_t)s * WCOLS + j * 4);
        }
        for (int idx = tid; idx < CC * 3 * XW; idx += 256) {
            int ci  = idx / (3 * XW);
            int rem = idx % (3 * XW);
            int ry  = rem / XW;
            int xx  = rem % XW;
            int gx  = xx - 1;
            int gy0 = y0 - 1 + ry;
            int gy1 = gy0 + 1;
            bool okx = (gx >= 0) && (gx < W);
            const float* src = chan_ptr(ci0 + ci) + gy0 * W + gx;
            u32 dst = sib + (u32)(buf * SM_IF + (ci * 3 + ry) * XW + xx) * 8u;
            cp4z(dst,     src,     okx && (gy0 >= 0) && (gy0 < H));
            cp4z(dst + 4, src + W, okx && (gy1 < H));
        }
        cp_commit();
    };

    stage(0, 0);
    stage(1, 1);

    for (int ck = 0; ck < NCK; ck++) {
        const int buf = ck % 3;
        if (ck + 2 < NCK)      { stage(ck + 2, (ck + 2) % 3); cp_wait2(); }
        else if (ck + 1 < NCK) { cp_wait1(); }
        else                   { cp_wait0(); }
        __syncthreads();

        const float*  wbuf = sW + buf * SM_WF;
        const float2* ibuf = sI + buf * SM_IF;
        for (int ci = 0; ci < CC; ++ci) {
#pragma unroll
            for (int ky = 0; ky < 3; ky++) {
                const ull* ip = reinterpret_cast<const ull*>(&ibuf[(ci * 3 + ky) * XW + x0]);
                ull vv[7];
#pragma unroll
                for (int j = 0; j < 7; j++) vv[j] = ip[j];
#pragma unroll
                for (int kx = 0; kx < 3; kx++) {
                    const int s = ci * KS2 + ky * 3 + kx;
                    const float* wp = &wbuf[s * CO_PAD + tco * RCO];
                    ull w2[RCO];
                    if (RCO == 4) {
                        float4 w4 = *reinterpret_cast<const float4*>(wp);
                        w2[0] = dup2(w4.x); w2[1] = dup2(w4.y);
                        w2[2] = dup2(w4.z); w2[3] = dup2(w4.w);
                    } else {
                        float2 wv = *reinterpret_cast<const float2*>(wp);
                        w2[0] = dup2(wv.x); w2[1] = dup2(wv.y);
                    }
#pragma unroll
                    for (int p = 0; p < 5; p++)
#pragma unroll
                        for (int r = 0; r < RCO; r++) ffma2(acc[r][p], w2[r], vv[kx + p]);
                }
            }
        }
        __syncthreads();
    }

    float* optr = (MODE == 0) ? g_h : (MODE == 3) ? g_off : out_param;
#pragma unroll
    for (int r = 0; r < RCO; r++) {
        int co = co_base + tco * RCO + r;
        if (co >= COUT) continue;
        float bnb, bns = 1.0f, rs = 0.0f;
        if (MODE == 1) {
            float gm = bias_or_bn[co];
            float bt = bias_or_bn[COUT + co];
            float mn = bias_or_bn[2 * COUT + co];
            float vr = bias_or_bn[3 * COUT + co];
            bns = gm * rsqrtf(vr + EPS);
            bnb = bt - mn * bns;
            rs  = *res_scale;
        } else {
            bnb = bias_or_bn[co];
        }
#pragma unroll
        for (int p = 0; p < 5; p++) {
            int x = x0 + p;
            int o0 = ((b * COUT + co) * H + y0) * W + x;
            int o1 = o0 + W;
            float a0, a1;
            unpack2(acc[r][p], a0, a1);
            if (MODE == 0) {
                optr[o0] = silu_(a0 + bnb);
                optr[o1] = silu_(a1 + bnb);
            } else if (MODE == 1) {
                optr[o0] = silu_(a0 * bns + bnb) + rs * g_iral[o0];
                optr[o1] = silu_(a1 * bns + bnb) + rs * g_iral[o1];
            } else {
                optr[o0] = a0 + bnb;
                optr[o1] = a1 + bnb;
            }
        }
    }
}

// ---------------------------------------------------------------------------
// DCN 1x1 conv (Cin=1152 -> 128), cp.async TRIPLE-buffered, cp16 weights
// ---------------------------------------------------------------------------
constexpr int DCC     = 32;
constexpr int DCO_T   = 64;
constexpr int DCO_PAD = 68;
constexpr int DIELEM  = DCC * W;
constexpr int DSM_W   = DCC * DCO_PAD;
constexpr int DSM_I   = DCC * W;
constexpr int DCN_SMEM = (3 * DSM_W) * 4 + (3 * DSM_I) * 8;   // 87552 B

__global__ __launch_bounds__(256)
void dcn_conv_kernel(const float* __restrict__ bias) {
    extern __shared__ float dsm[];
    float*  sW = dsm;
    float2* sI = (float2*)(dsm + 3 * DSM_W);

    const int tid = threadIdx.x;
    const int tco = tid & 15;
    const int tpx = tid >> 4;
    const int x0  = tpx * 5;
    const int b   = blockIdx.x / (H / 2);
    const int y0  = (blockIdx.x % (H / 2)) * 2;
    const int co_base = blockIdx.y * DCO_T;

    const u32 swb = smem_u32(sW);
    const u32 sib = smem_u32(sI);
    const float* vbase = g_vals + (size_t)b * KD * HW + (size_t)y0 * W;

    ull acc[4][5];
#pragma unroll
    for (int r = 0; r < 4; r++)
#pragma unroll
        for (int p = 0; p < 5; p++) acc[r][p] = 0ull;

    auto stage = [&](int ck, int buf) {
        const int ci0 = ck * DCC;
        const float* wsrc = g_wdt + (size_t)ci0 * CH + co_base;
#pragma unroll
        for (int i = 0; i < (DCC * 16) / 256; i++) {
            int idx = i * 256 + tid;
            int s = idx >> 4, j = idx & 15;
            cp16(swb + (u32)(buf * DSM_W + s * DCO_PAD + j * 4) * 4u,
                 wsrc + (size_t)s * CH + j * 4);
        }
#pragma unroll 2
        for (int i = 0; i < DIELEM / 256; i++) {
            int idx = i * 256 + tid;
            int ci = idx / W, xx = idx % W;
            const float* src = vbase + (size_t)(ci0 + ci) * HW + xx;
            u32 dst = sib + (u32)(buf * DSM_I + ci * W + xx) * 8u;
            cp4(dst, src);
            cp4(dst + 4, src + W);
        }
        cp_commit();
    };

    stage(0, 0);
    stage(1, 1);

    constexpr int NCK = KD / DCC;
    for (int ck = 0; ck < NCK; ck++) {
        const int buf = ck % 3;
        if (ck + 2 < NCK)      { stage(ck + 2, (ck + 2) % 3); cp_wait2(); }
        else if (ck + 1 < NCK) { cp_wait1(); }
        else                   { cp_wait0(); }
        __syncthreads();

        const float*  wbuf = sW + buf * DSM_W;
        const float2* ibuf = sI + buf * DSM_I;
#pragma unroll 4
        for (int ci = 0; ci < DCC; ++ci) {
            const ull* ip = reinterpret_cast<const ull*>(&ibuf[ci * W + x0]);
            ull vv[5];
#pragma unroll
            for (int p = 0; p < 5; p++) vv[p] = ip[p];
            float4 w4 = *reinterpret_cast<const float4*>(&wbuf[ci * DCO_PAD + tco * 4]);
            ull w2[4] = { dup2(w4.x), dup2(w4.y), dup2(w4.z), dup2(w4.w) };
#pragma unroll
            for (int p = 0; p < 5; p++)
#pragma unroll
                for (int r = 0; r < 4; r++) ffma2(acc[r][p], w2[r], vv[p]);
        }
        __syncthreads();
    }

#pragma unroll
    for (int r = 0; r < 4; r++) {
        int co = co_base + tco * 4 + r;
        float bs = __ldg(&bias[co]);
#pragma unroll
        for (int p = 0; p < 5; p++) {
            int x = x0 + p;
            int o0 = ((b * CH + co) * H + y0) * W + x;
            float a0, a1;
            unpack2(acc[r][p], a0, a1);
            g_iral[o0]     = a0 + bs;
            g_iral[o0 + W] = a1 + bs;
        }
    }
}

// ---------------------------------------------------------------------------
// Deformable bilinear sampling -> g_vals[b][c*9+k][y][x]
// ---------------------------------------------------------------------------
__global__ __launch_bounds__(256)
void deform_kernel(const float* __restrict__ ir) {
    const int blk   = blockIdx.x;
    const int ytile = blk % 27;
    const int bk    = blk / 27;
    const int k     = bk % 9;
    const int b     = bk / 9;
    const int tid   = threadIdx.x;
    if (tid >= 240) return;
    const int y = ytile * 3 + tid / 80;
    const int x = tid % 80;
    if (y >= H) return;

    const float* obase = g_off + (b * 27) * HW + y * W + x;
    float oy = obase[(2 * k) * HW];
    float ox = obase[(2 * k + 1) * HW];
    float m  = sigm_(obase[(18 + k) * HW]);

    const int ky = k / 3 - 1;
    const int kx = k % 3 - 1;
    float ys = oy + (float)(ky + y);
    float xs = ox + (float)(kx + x);
    float fy = floorf(ys), fx = floorf(xs);
    float wy = ys - fy,    wx = xs - fx;
    int y0 = (int)fy, x0 = (int)fx;
    int y1 = y0 + 1,  x1 = x0 + 1;
    bool vy0 = (y0 >= 0) && (y0 < H);
    bool vy1 = (y1 >= 0) && (y1 < H);
    bool vx0 = (x0 >= 0) && (x0 < W);
    bool vx1 = (x1 >= 0) && (x1 < W);
    float w00 = (1.0f - wy) * (1.0f - wx) * m * ((vy0 && vx0) ? 1.0f : 0.0f);
    float w01 = (1.0f - wy) * wx          * m * ((vy0 && vx1) ? 1.0f : 0.0f);
    float w10 = wy          * (1.0f - wx) * m * ((vy1 && vx0) ? 1.0f : 0.0f);
    float w11 = wy          * wx          * m * ((vy1 && vx1) ? 1.0f : 0.0f);
    int cy0 = min(max(y0, 0), H - 1), cy1 = min(max(y1, 0), H - 1);
    int cx0 = min(max(x0, 0), W - 1), cx1 = min(max(x1, 0), W - 1);
    int i00 = cy0 * W + cx0, i01 = cy0 * W + cx1;
    int i10 = cy1 * W + cx0, i11 = cy1 * W + cx1;

    const float* ib = ir + b * CH * HW;
    float* vout = g_vals + ((size_t)b * CH * 9 + k) * HW + y * W + x;
#pragma unroll 4
    for (int c = 0; c < CH; c++) {
        const float* p = ib + c * HW;
        float v = w00 * __ldg(p + i00) + w01 * __ldg(p + i01)
                + w10 * __ldg(p + i10) + w11 * __ldg(p + i11);
        vout[(size_t)c * 9 * HW] = v;
    }
}

// ---------------------------------------------------------------------------
// Gate stage 1: 1x1 conv 256 -> 16 + BN + SiLU -> g_g1
// ---------------------------------------------------------------------------
__global__ __launch_bounds__(256)
void gate1_kernel(const float* __restrict__ rgb,
                  const float* __restrict__ wg1,
                  const float* __restrict__ bng1) {
    __shared__ float sg[2 * CH * MID];
    const int tid = threadIdx.x;
    for (int i = tid; i < 2 * CH * MID; i += 256) {
        int ci = i >> 4, o = i & 15;
        sg[i] = wg1[o * (2 * CH) + ci];
    }
    __syncthreads();
    const int idx = blockIdx.x * 256 + tid;
    if (idx >= Bn * HW) return;
    const int b = idx / HW, p = idx % HW;

    float acc[MID];
#pragma unroll
    for (int o = 0; o < MID; o++) acc[o] = 0.0f;

    const float* rp = rgb    + b * CH * HW + p;
    const float* ip = g_iral + b * CH * HW + p;
    for (int ci = 0; ci < CH; ci++) {
        float v = rp[ci * HW];
        const float* w = &sg[ci * MID];
#pragma unroll
        for (int o = 0; o < MID; o++) acc[o] += w[o] * v;
    }
    for (int ci = 0; ci < CH; ci++) {
        float v = ip[ci * HW];
        const float* w = &sg[(CH + ci) * MID];
#pragma unroll
        for (int o = 0; o < MID; o++) acc[o] += w[o] * v;
    }
#pragma unroll
    for (int o = 0; o < MID; o++) {
        float gm = bng1[o], bt = bng1[MID + o];
        float mn = bng1[2 * MID + o], vr = bng1[3 * MID + o];
        float sc = gm * rsqrtf(vr + EPS);
        g_g1[(b * MID + o) * HW + p] = silu_(acc[o] * sc + bt - mn * sc);
    }
}

// ---------------------------------------------------------------------------
// Gate stages 2+3, then materialize fused conv input g_fin
// ---------------------------------------------------------------------------
__global__ __launch_bounds__(256)
void gate23_kernel(const float* __restrict__ wg2,
                   const float* __restrict__ bng2,
                   const float* __restrict__ wg3,
                   const float* __restrict__ bg3,
                   const float* __restrict__ rgb) {
    const int idx = blockIdx.x * 256 + threadIdx.x;
    if (idx >= Bn * HW) return;
    const int b = idx / HW, p = idx % HW;
    const int y = p / W, x = p % W;

    float s3 = __ldg(bg3);
#pragma unroll
    for (int o = 0; o < MID; o++) {
        const float* gp = g_g1 + (b * MID + o) * HW;
        float s = 0.0f;
#pragma unroll
        for (int ky = 0; ky < 3; ky++) {
            int yy = y + ky - 1;
            if (yy < 0 || yy >= H) continue;
#pragma unroll
            for (int kx = 0; kx < 3; kx++) {
                int xx = x + kx - 1;
                if (xx < 0 || xx >= W) continue;
                s += gp[yy * W + xx] * __ldg(&wg2[o * 9 + ky * 3 + kx]);
            }
        }
        float gm = __ldg(&bng2[o]), bt = __ldg(&bng2[MID + o]);
        float mn = __ldg(&bng2[2 * MID + o]), vr = __ldg(&bng2[3 * MID + o]);
        float sc = gm * rsqrtf(vr + EPS);
        s3 += silu_(s * sc + bt - mn * sc) * __ldg(&wg3[o]);
    }
    float gv = sigm_(s3);
    g_gate[b * HW + p] = gv;

    const float* ip = g_iral + (size_t)b * CH * HW + p;
    const float* rp = rgb    + (size_t)b * CH * HW + p;
    float* f0 = g_fin + (size_t)b * 2 * CH * HW + p;
    float* f1 = f0 + (size_t)CH * HW;
    float om = 1.0f - gv;
#pragma unroll 4
    for (int c = 0; c < CH; c++) {
        f0[(size_t)c * HW] = gv * ip[(size_t)c * HW];
        f1[(size_t)c * HW] = om * rp[(size_t)c * HW];
    }
}

// ---------------------------------------------------------------------------
// Launcher
// ---------------------------------------------------------------------------
extern "C" void kernel_launch(void* const* d_in, const int* in_sizes, int n_in,
                              void* d_out, int out_size) {
    const float* rgb    = (const float*)d_in[0];
    const float* ir     = (const float*)d_in[1];
    const float* w_off1 = (const float*)d_in[2];
    const float* b_off1 = (const float*)d_in[3];
    const float* w_off2 = (const float*)d_in[4];
    const float* b_off2 = (const float*)d_in[5];
    const float* w_dcn  = (const float*)d_in[6];
    const float* b_dcn  = (const float*)d_in[7];
    const float* w_g1   = (const float*)d_in[8];
    const float* bn_g1  = (const float*)d_in[9];
    const float* w_g2   = (const float*)d_in[10];
    const float* bn_g2  = (const float*)d_in[11];
    const float* w_g3   = (const float*)d_in[12];
    const float* b_g3   = (const float*)d_in[13];
    const float* w_f    = (const float*)d_in[14];
    const float* bn_f   = (const float*)d_in[15];
    const float* rscale = (const float*)d_in[16];
    float* out = (float*)d_out;

    float* w0t; cudaGetSymbolAddress((void**)&w0t, g_w0t);
    float* wft; cudaGetSymbolAddress((void**)&wft, g_wft);
    float* wdt; cudaGetSymbolAddress((void**)&wdt, g_wdt);
    float* w2t; cudaGetSymbolAddress((void**)&w2t, g_w2t);

    // triple-buffered smem sizes (bytes)
    const int sm_big = 3 * ((72 * 68) * 4 + (8 * 3 * 82) * 8);   // 105984 B
    const int sm_off = 3 * ((72 * 36) * 4 + (8 * 3 * 82) * 8);   // 78336 B

    cudaFuncSetAttribute(conv_kernel<0>, cudaFuncAttributeMaxDynamicSharedMemorySize, sm_big);
    cudaFuncSetAttribute(conv_kernel<1>, cudaFuncAttributeMaxDynamicSharedMemorySize, sm_big);
    cudaFuncSetAttribute(conv_kernel<3>, cudaFuncAttributeMaxDynamicSharedMemorySize, sm_off);
    cudaFuncSetAttribute(dcn_conv_kernel, cudaFuncAttributeMaxDynamicSharedMemorySize, DCN_SMEM);

    const int BX = Bn * (H / 2);   // 320 row-pair blocks

    // 0) weight transposes
    prep_w_kernel<<<(2304 * 128 + 255) / 256, 256>>>(w_off1, w0t, 2304, 128, 128);
    prep_w_kernel<<<(2304 * 128 + 255) / 256, 256>>>(w_f,    wft, 2304, 128, 128);
    prep_w_kernel<<<(1152 * 128 + 255) / 256, 256>>>(w_dcn,  wdt, 1152, 128, 128);
    prep_w_kernel<<<(1152 * 32 + 255) / 256, 256>>>(w_off2,  w2t, 1152, 32, 27);

    // 1) h = silu(conv3x3(concat(rgb, ir)))
    conv_kernel<0><<<dim3(BX, 2), 256, sm_big>>>(rgb, ir, w0t, b_off1, nullptr, nullptr);
    // 2) offset/mask conv (27 ch)
    conv_kernel<3><<<dim3(BX, 1), 256, sm_off>>>(nullptr, nullptr, w2t, b_off2, nullptr, nullptr);
    // 3) deformable bilinear sampling * mask -> g_vals
    deform_kernel<<<Bn * 9 * 27, 256>>>(ir);
    // 4) ir_aligned = vals . w_dcn + b_dcn
    dcn_conv_kernel<<<dim3(BX, 2), 256, DCN_SMEM>>>(b_dcn);
    // 5) gate stage 1
    gate1_kernel<<<(Bn * HW + 255) / 256, 256>>>(rgb, w_g1, bn_g1);
    // 6) gate stages 2+3 + fused-input materialization
    gate23_kernel<<<(Bn * HW + 255) / 256, 256>>>(w_g2, bn_g2, w_g3, b_g3, rgb);
    // 7) fused conv + BN + SiLU + residual -> out
    conv_kernel<1><<<dim3(BX, 2), 256, sm_big>>>(nullptr, nullptr, wft, bn_f, rscale, out);
}

// round 12
// speedup vs baseline: 1.8422x; 1.0662x over previous
#include <cuda_runtime.h>

// ---------------------------------------------------------------------------
// Problem constants
// ---------------------------------------------------------------------------
constexpr int Bn  = 8;
constexpr int CH  = 128;
constexpr int H   = 80;
constexpr int W   = 80;
constexpr int HW  = H * W;
constexpr int MID = 16;
constexpr int KD  = CH * 9;          // 1152
constexpr float EPS = 1e-5f;

// tail-split constants: 640 tiles = 592 (2 exact waves at 296 slots) + 48,
// the 48 leftovers run as 96 half-co tiles in one short wave.
constexpr int NTILE   = 640;         // (320 row-pairs) x (2 co-halves)
constexpr int NA      = 592;
constexpr int RP_TAIL = 272;         // tail covers row-pairs 272..319, co 64..127

// ---------------------------------------------------------------------------
// Scratch
// ---------------------------------------------------------------------------
__device__ float g_h[Bn * CH * HW];
__device__ float g_off[Bn * 27 * HW];
__device__ float g_vals[(size_t)Bn * CH * 9 * HW];   // [b][c*9+k][y][x]
__device__ float g_iral[Bn * CH * HW];
__device__ float g_g1[Bn * MID * HW];
__device__ float g_gate[Bn * HW];
__device__ float g_fin[Bn * 2 * CH * HW];            // fused conv input concat
// transposed weights [k][co] (row-major, contiguous in co) for cp16 staging
__device__ float g_w0t[2 * CH * 9 * CH];             // 2304 x 128
__device__ float g_wft[2 * CH * 9 * CH];             // 2304 x 128
__device__ float g_wdt[KD * CH];                     // 1152 x 128
__device__ float g_w2t[KD * 32];                     // 1152 x 32 (27 zero-padded)

#define DEV __device__ __forceinline__
typedef unsigned long long ull;
typedef unsigned int u32;

DEV float sigm_(float x) { return 1.0f / (1.0f + __expf(-x)); }
DEV float silu_(float x) { return x * sigm_(x); }

DEV void ffma2(ull& d, ull a, ull b) {
    asm("fma.rn.f32x2 %0, %1, %2, %0;" : "+l"(d) : "l"(a), "l"(b));
}
DEV ull dup2(float w) { ull u; asm("mov.b64 %0, {%1, %1};" : "=l"(u) : "f"(w)); return u; }
DEV void unpack2(ull u, float& x, float& y) {
    asm("mov.b64 {%0, %1}, %2;" : "=f"(x), "=f"(y) : "l"(u));
}
DEV u32 smem_u32(const void* p) {
    u32 a; asm("{ .reg .u64 t; cvta.to.shared.u64 t, %1; cvt.u32.u64 %0, t; }" : "=r"(a) : "l"(p));
    return a;
}
DEV void cp4(u32 dst, const float* src) {
    asm volatile("cp.async.ca.shared.global [%0], [%1], 4;" :: "r"(dst), "l"(src) : "memory");
}
DEV void cp16(u32 dst, const float* src) {
    asm volatile("cp.async.cg.shared.global [%0], [%1], 16;" :: "r"(dst), "l"(src) : "memory");
}
DEV void cp4z(u32 dst, const float* src, bool ok) {
    int sz = ok ? 4 : 0;
    asm volatile("cp.async.ca.shared.global [%0], [%1], 4, %2;"
                 :: "r"(dst), "l"(src), "r"(sz) : "memory");
}
DEV void cp_commit() { asm volatile("cp.async.commit_group;" ::: "memory"); }
DEV void cp_wait1()  { asm volatile("cp.async.wait_group 1;" ::: "memory"); }
DEV void cp_wait0()  { asm volatile("cp.async.wait_group 0;" ::: "memory"); }

// ---------------------------------------------------------------------------
// Weight transpose prep: src [co][K] -> dst [K][cols] (cols >= cout, padded 0)
// ---------------------------------------------------------------------------
__global__ __launch_bounds__(256)
void prep_w_kernel(const float* __restrict__ src, float* __restrict__ dst,
                   int K, int cols, int cout) {
    int idx = blockIdx.x * 256 + threadIdx.x;
    if (idx >= K * cols) return;
    int r = idx / cols, co = idx % cols;
    dst[idx] = (co < cout) ? src[(size_t)co * K + r] : 0.0f;
}

// ---------------------------------------------------------------------------
// 3x3 tiled conv, cp.async double-buffered, cp16 weight staging, tail-split.
//   MODE 0: concat(rgb, ir)  Cin=256 -> g_h   (silu(v+b))
//   MODE 1: g_fin            Cin=256 -> out   (silu(bn)+res)
//   MODE 3: g_h              Cin=128 -> g_off (v+b)   [RCO=2, grid=row-pairs]
// RCO=4: linear tile id over (320 rp x 2 co-halves), grid = NA.
// RCO=2 (modes 0/1): tail mapping, grid = 96 (rp 272..319 x co quarters 64/96).
// ---------------------------------------------------------------------------
template <int MODE, int RCO>
__global__ __launch_bounds__(256)
void conv_kernel(const float* __restrict__ A, const float* __restrict__ Bp,
                 const float* __restrict__ wT,
                 const float* __restrict__ bias_or_bn,
                 const float* __restrict__ res_scale,
                 float* __restrict__ out_param) {
    constexpr int KS2  = 9;
    constexpr int CIN  = (MODE == 3) ? CH : 2 * CH;
    constexpr int COUT = (MODE == 3) ? 27 : CH;
    constexpr int CO_TILE = 16 * RCO;
    constexpr int CO_PAD  = CO_TILE + 4;
    constexpr int WCOLS = (MODE == 3) ? 32 : 128;
    constexpr int CC   = 8;
    constexpr int S    = CC * KS2;                  // 72
    constexpr int XW   = W + 2;
    constexpr int SM_WF = S * CO_PAD;
    constexpr int SM_IF = CC * 3 * XW;
    constexpr int NCK  = CIN / CC;
    constexpr int NW16 = S * (CO_TILE / 4);

    extern __shared__ float sm[];
    float*  sW = sm;                               // [2][SM_WF]
    float2* sI = (float2*)(sm + 2 * SM_WF);        // [2][SM_IF]

    const int tid = threadIdx.x;
    const int tco = tid & 15;
    const int tpx = tid >> 4;
    const int x0  = tpx * 5;

    int bx, co_base;
    if (MODE == 3) {                 // offset conv: grid = 320 row-pairs
        bx = blockIdx.x; co_base = 0;
    } else if (RCO == 4) {           // main body: linear tiles 0..NA-1
        int t = blockIdx.x;
        bx = t % 320; co_base = (t / 320) * 64;
    } else {                         // tail: 96 quarter-co tiles
        bx = RP_TAIL + (blockIdx.x >> 1);
        co_base = 64 + 32 * (blockIdx.x & 1);
    }
    const int b  = bx / (H / 2);
    const int y0 = (bx % (H / 2)) * 2;

    const u32 swb = smem_u32(sW);
    const u32 sib = smem_u32(sI);

    ull acc[RCO][5];
#pragma unroll
    for (int r = 0; r < RCO; r++)
#pragma unroll
        for (int p = 0; p < 5; p++) acc[r][p] = 0ull;

    auto chan_ptr = [&](int ci) -> const float* {
        if (MODE == 0) return (ci < CH) ? A + (size_t)(b * CH + ci) * HW
                                        : Bp + (size_t)(b * CH + (ci - CH)) * HW;
        else if (MODE == 1) return g_fin + (size_t)(b * 2 * CH + ci) * HW;
        else return g_h + (size_t)(b * CH + ci) * HW;
    };

    auto stage = [&](int ck, int buf) {
        const int ci0 = ck * CC;
        const float* wsrc = wT + (size_t)(ci0 * 9) * WCOLS + co_base;
        for (int idx = tid; idx < NW16; idx += 256) {
            int s = idx / (CO_TILE / 4), j = idx % (CO_TILE / 4);
            cp16(swb + (u32)(buf * SM_WF + s * CO_PAD + j * 4) * 4u,
                 wsrc + (size_t)s * WCOLS + j * 4);
        }
        for (int idx = tid; idx < CC * 3 * XW; idx += 256) {
            int ci  = idx / (3 * XW);
            int rem = idx % (3 * XW);
            int ry  = rem / XW;
            int xx  = rem % XW;
            int gx  = xx - 1;
            int gy0 = y0 - 1 + ry;
            int gy1 = gy0 + 1;
            bool okx = (gx >= 0) && (gx < W);
            const float* src = chan_ptr(ci0 + ci) + gy0 * W + gx;
            u32 dst = sib + (u32)(buf * SM_IF + (ci * 3 + ry) * XW + xx) * 8u;
            cp4z(dst,     src,     okx && (gy0 >= 0) && (gy0 < H));
            cp4z(dst + 4, src + W, okx && (gy1 < H));
        }
        cp_commit();
    };

    stage(0, 0);

    for (int ck = 0; ck < NCK; ck++) {
        const int buf = ck & 1;
        if (ck + 1 < NCK) { stage(ck + 1, buf ^ 1); cp_wait1(); }
        else              { cp_wait0(); }
        __syncthreads();

        const float*  wbuf = sW + buf * SM_WF;
        const float2* ibuf = sI + buf * SM_IF;
        for (int ci = 0; ci < CC; ++ci) {
#pragma unroll
            for (int ky = 0; ky < 3; ky++) {
                const ull* ip = reinterpret_cast<const ull*>(&ibuf[(ci * 3 + ky) * XW + x0]);
                ull vv[7];
#pragma unroll
                for (int j = 0; j < 7; j++) vv[j] = ip[j];
#pragma unroll
                for (int kx = 0; kx < 3; kx++) {
                    const int s = ci * KS2 + ky * 3 + kx;
                    const float* wp = &wbuf[s * CO_PAD + tco * RCO];
                    ull w2[RCO];
                    if (RCO == 4) {
                        float4 w4 = *reinterpret_cast<const float4*>(wp);
                        w2[0] = dup2(w4.x); w2[1] = dup2(w4.y);
                        w2[2] = dup2(w4.z); w2[3] = dup2(w4.w);
                    } else {
                        float2 wv = *reinterpret_cast<const float2*>(wp);
                        w2[0] = dup2(wv.x); w2[1] = dup2(wv.y);
                    }
#pragma unroll
                    for (int p = 0; p < 5; p++)
#pragma unroll
                        for (int r = 0; r < RCO; r++) ffma2(acc[r][p], w2[r], vv[kx + p]);
                }
            }
        }
        __syncthreads();
    }

    float* optr = (MODE == 0) ? g_h : (MODE == 3) ? g_off : out_param;
#pragma unroll
    for (int r = 0; r < RCO; r++) {
        int co = co_base + tco * RCO + r;
        if (co >= COUT) continue;
        float bnb, bns = 1.0f, rs = 0.0f;
        if (MODE == 1) {
            float gm = bias_or_bn[co];
            float bt = bias_or_bn[COUT + co];
            float mn = bias_or_bn[2 * COUT + co];
            float vr = bias_or_bn[3 * COUT + co];
            bns = gm * rsqrtf(vr + EPS);
            bnb = bt - mn * bns;
            rs  = *res_scale;
        } else {
            bnb = bias_or_bn[co];
        }
#pragma unroll
        for (int p = 0; p < 5; p++) {
            int x = x0 + p;
            int o0 = ((b * COUT + co) * H + y0) * W + x;
            int o1 = o0 + W;
            float a0, a1;
            unpack2(acc[r][p], a0, a1);
            if (MODE == 0) {
                optr[o0] = silu_(a0 + bnb);
                optr[o1] = silu_(a1 + bnb);
            } else if (MODE == 1) {
                optr[o0] = silu_(a0 * bns + bnb) + rs * g_iral[o0];
                optr[o1] = silu_(a1 * bns + bnb) + rs * g_iral[o1];
            } else {
                optr[o0] = a0 + bnb;
                optr[o1] = a1 + bnb;
            }
        }
    }
}

// ---------------------------------------------------------------------------
// DCN 1x1 conv (Cin=1152 -> 128), cp.async double-buffered, tail-split.
// RCO=4: linear tiles (grid NA). RCO=2: tail (grid 96).
// ---------------------------------------------------------------------------
constexpr int DCC    = 32;
constexpr int DIELEM = DCC * W;
constexpr int DSM_I  = DCC * W;

template <int RCO>
__global__ __launch_bounds__(256)
void dcn_conv_kernel(const float* __restrict__ bias) {
    constexpr int CO_T   = 16 * RCO;
    constexpr int CO_PAD = CO_T + 4;
    constexpr int DSM_W  = DCC * CO_PAD;
    constexpr int NW16   = DCC * (CO_T / 4);

    extern __shared__ float dsm[];
    float*  sW = dsm;                              // [2][DSM_W]
    float2* sI = (float2*)(dsm + 2 * DSM_W);       // [2][DSM_I]

    const int tid = threadIdx.x;
    const int tco = tid & 15;
    const int tpx = tid >> 4;
    const int x0  = tpx * 5;

    int bx, co_base;
    if (RCO == 4) {
        int t = blockIdx.x;
        bx = t % 320; co_base = (t / 320) * 64;
    } else {
        bx = RP_TAIL + (blockIdx.x >> 1);
        co_base = 64 + 32 * (blockIdx.x & 1);
    }
    const int b  = bx / (H / 2);
    const int y0 = (bx % (H / 2)) * 2;

    const u32 swb = smem_u32(sW);
    const u32 sib = smem_u32(sI);
    const float* vbase = g_vals + (size_t)b * KD * HW + (size_t)y0 * W;

    ull acc[RCO][5];
#pragma unroll
    for (int r = 0; r < RCO; r++)
#pragma unroll
        for (int p = 0; p < 5; p++) acc[r][p] = 0ull;

    auto stage = [&](int ck, int buf) {
        const int ci0 = ck * DCC;
        const float* wsrc = g_wdt + (size_t)ci0 * CH + co_base;
        for (int idx = tid; idx < NW16; idx += 256) {
            int s = idx / (CO_T / 4), j = idx % (CO_T / 4);
            cp16(swb + (u32)(buf * DSM_W + s * CO_PAD + j * 4) * 4u,
                 wsrc + (size_t)s * CH + j * 4);
        }
        for (int idx = tid; idx < DIELEM; idx += 256) {
            int ci = idx / W, xx = idx % W;
            const float* src = vbase + (size_t)(ci0 + ci) * HW + xx;
            u32 dst = sib + (u32)(buf * DSM_I + ci * W + xx) * 8u;
            cp4(dst, src);
            cp4(dst + 4, src + W);
        }
        cp_commit();
    };

    stage(0, 0);

    constexpr int NCK = KD / DCC;
    for (int ck = 0; ck < NCK; ck++) {
        const int buf = ck & 1;
        if (ck + 1 < NCK) { stage(ck + 1, buf ^ 1); cp_wait1(); }
        else              { cp_wait0(); }
        __syncthreads();

        const float*  wbuf = sW + buf * DSM_W;
        const float2* ibuf = sI + buf * DSM_I;
#pragma unroll 4
        for (int ci = 0; ci < DCC; ++ci) {
            const ull* ip = reinterpret_cast<const ull*>(&ibuf[ci * W + x0]);
            ull vv[5];
#pragma unroll
            for (int p = 0; p < 5; p++) vv[p] = ip[p];
            ull w2[RCO];
            if (RCO == 4) {
                float4 w4 = *reinterpret_cast<const float4*>(&wbuf[ci * CO_PAD + tco * 4]);
                w2[0] = dup2(w4.x); w2[1] = dup2(w4.y);
                w2[2] = dup2(w4.z); w2[3] = dup2(w4.w);
            } else {
                float2 wv = *reinterpret_cast<const float2*>(&wbuf[ci * CO_PAD + tco * 2]);
                w2[0] = dup2(wv.x); w2[1] = dup2(wv.y);
            }
#pragma unroll
            for (int p = 0; p < 5; p++)
#pragma unroll
                for (int r = 0; r < RCO; r++) ffma2(acc[r][p], w2[r], vv[p]);
        }
        __syncthreads();
    }

#pragma unroll
    for (int r = 0; r < RCO; r++) {
        int co = co_base + tco * RCO + r;
        float bs = __ldg(&bias[co]);
#pragma unroll
        for (int p = 0; p < 5; p++) {
            int x = x0 + p;
            int o0 = ((b * CH + co) * H + y0) * W + x;
            float a0, a1;
            unpack2(acc[r][p], a0, a1);
            g_iral[o0]     = a0 + bs;
            g_iral[o0 + W] = a1 + bs;
        }
    }
}

// ---------------------------------------------------------------------------
// Deformable bilinear sampling -> g_vals[b][c*9+k][y][x]
// ---------------------------------------------------------------------------
__global__ __launch_bounds__(256)
void deform_kernel(const float* __restrict__ ir) {
    const int blk   = blockIdx.x;
    const int ytile = blk % 27;
    const int bk    = blk / 27;
    const int k     = bk % 9;
    const int b     = bk / 9;
    const int tid   = threadIdx.x;
    if (tid >= 240) return;
    const int y = ytile * 3 + tid / 80;
    const int x = tid % 80;
    if (y >= H) return;

    const float* obase = g_off + (b * 27) * HW + y * W + x;
    float oy = obase[(2 * k) * HW];
    float ox = obase[(2 * k + 1) * HW];
    float m  = sigm_(obase[(18 + k) * HW]);

    const int ky = k / 3 - 1;
    const int kx = k % 3 - 1;
    float ys = oy + (float)(ky + y);
    float xs = ox + (float)(kx + x);
    float fy = floorf(ys), fx = floorf(xs);
    float wy = ys - fy,    wx = xs - fx;
    int y0 = (int)fy, x0 = (int)fx;
    int y1 = y0 + 1,  x1 = x0 + 1;
    bool vy0 = (y0 >= 0) && (y0 < H);
    bool vy1 = (y1 >= 0) && (y1 < H);
    bool vx0 = (x0 >= 0) && (x0 < W);
    bool vx1 = (x1 >= 0) && (x1 < W);
    float w00 = (1.0f - wy) * (1.0f - wx) * m * ((vy0 && vx0) ? 1.0f : 0.0f);
    float w01 = (1.0f - wy) * wx          * m * ((vy0 && vx1) ? 1.0f : 0.0f);
    float w10 = wy          * (1.0f - wx) * m * ((vy1 && vx0) ? 1.0f : 0.0f);
    float w11 = wy          * wx          * m * ((vy1 && vx1) ? 1.0f : 0.0f);
    int cy0 = min(max(y0, 0), H - 1), cy1 = min(max(y1, 0), H - 1);
    int cx0 = min(max(x0, 0), W - 1), cx1 = min(max(x1, 0), W - 1);
    int i00 = cy0 * W + cx0, i01 = cy0 * W + cx1;
    int i10 = cy1 * W + cx0, i11 = cy1 * W + cx1;

    const float* ib = ir + b * CH * HW;
    float* vout = g_vals + ((size_t)b * CH * 9 + k) * HW + y * W + x;
#pragma unroll 4
    for (int c = 0; c < CH; c++) {
        const float* p = ib + c * HW;
        float v = w00 * __ldg(p + i00) + w01 * __ldg(p + i01)
                + w10 * __ldg(p + i10) + w11 * __ldg(p + i11);
        vout[(size_t)c * 9 * HW] = v;
    }
}

// ---------------------------------------------------------------------------
// Gate stage 1: 1x1 conv 256 -> 16 + BN + SiLU -> g_g1
// ---------------------------------------------------------------------------
__global__ __launch_bounds__(256)
void gate1_kernel(const float* __restrict__ rgb,
                  const float* __restrict__ wg1,
                  const float* __restrict__ bng1) {
    __shared__ float sg[2 * CH * MID];
    const int tid = threadIdx.x;
    for (int i = tid; i < 2 * CH * MID; i += 256) {
        int ci = i >> 4, o = i & 15;
        sg[i] = wg1[o * (2 * CH) + ci];
    }
    __syncthreads();
    const int idx = blockIdx.x * 256 + tid;
    if (idx >= Bn * HW) return;
    const int b = idx / HW, p = idx % HW;

    float acc[MID];
#pragma unroll
    for (int o = 0; o < MID; o++) acc[o] = 0.0f;

    const float* rp = rgb    + b * CH * HW + p;
    const float* ip = g_iral + b * CH * HW + p;
    for (int ci = 0; ci < CH; ci++) {
        float v = rp[ci * HW];
        const float* w = &sg[ci * MID];
#pragma unroll
        for (int o = 0; o < MID; o++) acc[o] += w[o] * v;
    }
    for (int ci = 0; ci < CH; ci++) {
        float v = ip[ci * HW];
        const float* w = &sg[(CH + ci) * MID];
#pragma unroll
        for (int o = 0; o < MID; o++) acc[o] += w[o] * v;
    }
#pragma unroll
    for (int o = 0; o < MID; o++) {
        float gm = bng1[o], bt = bng1[MID + o];
        float mn = bng1[2 * MID + o], vr = bng1[3 * MID + o];
        float sc = gm * rsqrtf(vr + EPS);
        g_g1[(b * MID + o) * HW + p] = silu_(acc[o] * sc + bt - mn * sc);
    }
}

// ---------------------------------------------------------------------------
// Gate stages 2+3, then materialize fused conv input g_fin
// ---------------------------------------------------------------------------
__global__ __launch_bounds__(256)
void gate23_kernel(const float* __restrict__ wg2,
                   const float* __restrict__ bng2,
                   const float* __restrict__ wg3,
                   const float* __restrict__ bg3,
                   const float* __restrict__ rgb) {
    const int idx = blockIdx.x * 256 + threadIdx.x;
    if (idx >= Bn * HW) return;
    const int b = idx / HW, p = idx % HW;
    const int y = p / W, x = p % W;

    float s3 = __ldg(bg3);
#pragma unroll
    for (int o = 0; o < MID; o++) {
        const float* gp = g_g1 + (b * MID + o) * HW;
        float s = 0.0f;
#pragma unroll
        for (int ky = 0; ky < 3; ky++) {
            int yy = y + ky - 1;
            if (yy < 0 || yy >= H) continue;
#pragma unroll
            for (int kx = 0; kx < 3; kx++) {
                int xx = x + kx - 1;
                if (xx < 0 || xx >= W) continue;
                s += gp[yy * W + xx] * __ldg(&wg2[o * 9 + ky * 3 + kx]);
            }
        }
        float gm = __ldg(&bng2[o]), bt = __ldg(&bng2[MID + o]);
        float mn = __ldg(&bng2[2 * MID + o]), vr = __ldg(&bng2[3 * MID + o]);
        float sc = gm * rsqrtf(vr + EPS);
        s3 += silu_(s * sc + bt - mn * sc) * __ldg(&wg3[o]);
    }
    float gv = sigm_(s3);
    g_gate[b * HW + p] = gv;

    const float* ip = g_iral + (size_t)b * CH * HW + p;
    const float* rp = rgb    + (size_t)b * CH * HW + p;
    float* f0 = g_fin + (size_t)b * 2 * CH * HW + p;
    float* f1 = f0 + (size_t)CH * HW;
    float om = 1.0f - gv;
#pragma unroll 4
    for (int c = 0; c < CH; c++) {
        f0[(size_t)c * HW] = gv * ip[(size_t)c * HW];
        f1[(size_t)c * HW] = om * rp[(size_t)c * HW];
    }
}

// ---------------------------------------------------------------------------
// Launcher
// ---------------------------------------------------------------------------
extern "C" void kernel_launch(void* const* d_in, const int* in_sizes, int n_in,
                              void* d_out, int out_size) {
    const float* rgb    = (const float*)d_in[0];
    const float* ir     = (const float*)d_in[1];
    const float* w_off1 = (const float*)d_in[2];
    const float* b_off1 = (const float*)d_in[3];
    const float* w_off2 = (const float*)d_in[4];
    const float* b_off2 = (const float*)d_in[5];
    const float* w_dcn  = (const float*)d_in[6];
    const float* b_dcn  = (const float*)d_in[7];
    const float* w_g1   = (const float*)d_in[8];
    const float* bn_g1  = (const float*)d_in[9];
    const float* w_g2   = (const float*)d_in[10];
    const float* bn_g2  = (const float*)d_in[11];
    const float* w_g3   = (const float*)d_in[12];
    const float* b_g3   = (const float*)d_in[13];
    const float* w_f    = (const float*)d_in[14];
    const float* bn_f   = (const float*)d_in[15];
    const float* rscale = (const float*)d_in[16];
    float* out = (float*)d_out;

    float* w0t; cudaGetSymbolAddress((void**)&w0t, g_w0t);
    float* wft; cudaGetSymbolAddress((void**)&wft, g_wft);
    float* wdt; cudaGetSymbolAddress((void**)&wdt, g_wdt);
    float* w2t; cudaGetSymbolAddress((void**)&w2t, g_w2t);

    // double-buffered smem sizes
    const int sm_big4 = 2 * ((72 * 68) * 4 + (8 * 3 * 82) * 8);   // 70656 B
    const int sm_big2 = 2 * ((72 * 36) * 4 + (8 * 3 * 82) * 8);   // 52224 B
    const int sm_dcn4 = 2 * ((DCC * 68) * 4 + DSM_I * 8);         // 58368 B
    const int sm_dcn2 = 2 * ((DCC * 36) * 4 + DSM_I * 8);         // 50176 B

    cudaFuncSetAttribute(conv_kernel<0, 4>, cudaFuncAttributeMaxDynamicSharedMemorySize, sm_big4);
    cudaFuncSetAttribute(conv_kernel<0, 2>, cudaFuncAttributeMaxDynamicSharedMemorySize, sm_big2);
    cudaFuncSetAttribute(conv_kernel<1, 4>, cudaFuncAttributeMaxDynamicSharedMemorySize, sm_big4);
    cudaFuncSetAttribute(conv_kernel<1, 2>, cudaFuncAttributeMaxDynamicSharedMemorySize, sm_big2);
    cudaFuncSetAttribute(conv_kernel<3, 2>, cudaFuncAttributeMaxDynamicSharedMemorySize, sm_big2);
    cudaFuncSetAttribute(dcn_conv_kernel<4>, cudaFuncAttributeMaxDynamicSharedMemorySize, sm_dcn4);
    cudaFuncSetAttribute(dcn_conv_kernel<2>, cudaFuncAttributeMaxDynamicSharedMemorySize, sm_dcn2);

    // 0) weight transposes
    prep_w_kernel<<<(2304 * 128 + 255) / 256, 256>>>(w_off1, w0t, 2304, 128, 128);
    prep_w_kernel<<<(2304 * 128 + 255) / 256, 256>>>(w_f,    wft, 2304, 128, 128);
    prep_w_kernel<<<(1152 * 128 + 255) / 256, 256>>>(w_dcn,  wdt, 1152, 128, 128);
    prep_w_kernel<<<(1152 * 32 + 255) / 256, 256>>>(w_off2,  w2t, 1152, 32, 27);

    // 1) h = silu(conv3x3(concat(rgb, ir)))  — A (592 tiles) + B tail (96)
    conv_kernel<0, 4><<<NA, 256, sm_big4>>>(rgb, ir, w0t, b_off1, nullptr, nullptr);
    conv_kernel<0, 2><<<2 * (NTILE - NA), 256, sm_big2>>>(rgb, ir, w0t, b_off1, nullptr, nullptr);
    // 2) offset/mask conv (27 ch)
    conv_kernel<3, 2><<<320, 256, sm_big2>>>(nullptr, nullptr, w2t, b_off2, nullptr, nullptr);
    // 3) deformable bilinear sampling * mask -> g_vals
    deform_kernel<<<Bn * 9 * 27, 256>>>(ir);
    // 4) ir_aligned = vals . w_dcn + b_dcn — A + B tail
    dcn_conv_kernel<4><<<NA, 256, sm_dcn4>>>(b_dcn);
    dcn_conv_kernel<2><<<2 * (NTILE - NA), 256, sm_dcn2>>>(b_dcn);
    // 5) gate stage 1
    gate1_kernel<<<(Bn * HW + 255) / 256, 256>>>(rgb, w_g1, bn_g1);
    // 6) gate stages 2+3 + fused-input materialization
    gate23_kernel<<<(Bn * HW + 255) / 256, 256>>>(w_g2, bn_g2, w_g3, b_g3, rgb);
    // 7) fused conv + BN + SiLU + residual -> out — A + B tail
    conv_kernel<1, 4><<<NA, 256, sm_big4>>>(nullptr, nullptr, wft, bn_f, rscale, out);
    conv_kernel<1, 2><<<2 * (NTILE - NA), 256, sm_big2>>>(nullptr, nullptr, wft, bn_f, rscale, out);
}

// round 13
// speedup vs baseline: 1.8885x; 1.0252x over previous
#include <cuda_runtime.h>

// ---------------------------------------------------------------------------
// Problem constants
// ---------------------------------------------------------------------------
constexpr int Bn  = 8;
constexpr int CH  = 128;
constexpr int H   = 80;
constexpr int W   = 80;
constexpr int HW  = H * W;
constexpr int MID = 16;
constexpr int KD  = CH * 9;          // 1152
constexpr float EPS = 1e-5f;

// tail-split: 640 tiles = 592 full (2 exact waves at 296 slots) + 48 -> 96 halves
constexpr int NTILE   = 640;
constexpr int NA      = 592;
constexpr int NBLK    = NA + 2 * (NTILE - NA);   // 688 blocks per heavy conv
constexpr int RP_TAIL = 272;

// ---------------------------------------------------------------------------
// Scratch
// ---------------------------------------------------------------------------
__device__ float g_h[Bn * CH * HW];
__device__ float g_off[Bn * 27 * HW];
__device__ float g_vals[(size_t)Bn * CH * 9 * HW];   // [b][c*9+k][y][x]
__device__ float g_iral[Bn * CH * HW];
__device__ float g_g1[Bn * MID * HW];
__device__ float g_gate[Bn * HW];
__device__ float g_fin[Bn * 2 * CH * HW];
// transposed weights [k][co]
__device__ float g_w0t[2 * CH * 9 * CH];
__device__ float g_wft[2 * CH * 9 * CH];
__device__ float g_wdt[KD * CH];
__device__ float g_w2t[KD * 32];

#define DEV __device__ __forceinline__
typedef unsigned long long ull;
typedef unsigned int u32;

DEV float sigm_(float x) { return 1.0f / (1.0f + __expf(-x)); }
DEV float silu_(float x) { return x * sigm_(x); }

DEV void ffma2(ull& d, ull a, ull b) {
    asm("fma.rn.f32x2 %0, %1, %2, %0;" : "+l"(d) : "l"(a), "l"(b));
}
DEV ull dup2(float w) { ull u; asm("mov.b64 %0, {%1, %1};" : "=l"(u) : "f"(w)); return u; }
DEV void unpack2(ull u, float& x, float& y) {
    asm("mov.b64 {%0, %1}, %2;" : "=f"(x), "=f"(y) : "l"(u));
}
DEV u32 smem_u32(const void* p) {
    u32 a; asm("{ .reg .u64 t; cvta.to.shared.u64 t, %1; cvt.u32.u64 %0, t; }" : "=r"(a) : "l"(p));
    return a;
}
DEV void cp4(u32 dst, const float* src) {
    asm volatile("cp.async.ca.shared.global [%0], [%1], 4;" :: "r"(dst), "l"(src) : "memory");
}
DEV void cp16(u32 dst, const float* src) {
    asm volatile("cp.async.cg.shared.global [%0], [%1], 16;" :: "r"(dst), "l"(src) : "memory");
}
DEV void cp4z(u32 dst, const float* src, bool ok) {
    int sz = ok ? 4 : 0;
    asm volatile("cp.async.ca.shared.global [%0], [%1], 4, %2;"
                 :: "r"(dst), "l"(src), "r"(sz) : "memory");
}
DEV void cp_commit() { asm volatile("cp.async.commit_group;" ::: "memory"); }
DEV void cp_wait1()  { asm volatile("cp.async.wait_group 1;" ::: "memory"); }
DEV void cp_wait0()  { asm volatile("cp.async.wait_group 0;" ::: "memory"); }

// ---------------------------------------------------------------------------
// Weight transpose prep
// ---------------------------------------------------------------------------
__global__ __launch_bounds__(256)
void prep_w_kernel(const float* __restrict__ src, float* __restrict__ dst,
                   int K, int cols, int cout) {
    int idx = blockIdx.x * 256 + threadIdx.x;
    if (idx >= K * cols) return;
    int r = idx / cols, co = idx % cols;
    dst[idx] = (co < cout) ? src[(size_t)co * K + r] : 0.0f;
}

// ---------------------------------------------------------------------------
// 3x3 conv body (device function), cp.async double-buffered.
// ---------------------------------------------------------------------------
template <int MODE, int RCO>
DEV void conv_body(const float* __restrict__ A, const float* __restrict__ Bp,
                   const float* __restrict__ wT,
                   const float* __restrict__ bias_or_bn,
                   const float* __restrict__ res_scale,
                   float* __restrict__ out_param,
                   float* sm, int bx, int co_base) {
    constexpr int KS2  = 9;
    constexpr int CIN  = (MODE == 3) ? CH : 2 * CH;
    constexpr int COUT = (MODE == 3) ? 27 : CH;
    constexpr int CO_TILE = 16 * RCO;
    constexpr int CO_PAD  = CO_TILE + 4;
    constexpr int WCOLS = (MODE == 3) ? 32 : 128;
    constexpr int CC   = 8;
    constexpr int S    = CC * KS2;                  // 72
    constexpr int XW   = W + 2;
    constexpr int SM_WF = S * CO_PAD;
    constexpr int SM_IF = CC * 3 * XW;
    constexpr int NCK  = CIN / CC;
    constexpr int NW16 = S * (CO_TILE / 4);

    float*  sW = sm;                               // [2][SM_WF]
    float2* sI = (float2*)(sm + 2 * SM_WF);        // [2][SM_IF]

    const int tid = threadIdx.x;
    const int tco = tid & 15;
    const int tpx = tid >> 4;
    const int x0  = tpx * 5;
    const int b  = bx / (H / 2);
    const int y0 = (bx % (H / 2)) * 2;

    const u32 swb = smem_u32(sW);
    const u32 sib = smem_u32(sI);

    ull acc[RCO][5];
#pragma unroll
    for (int r = 0; r < RCO; r++)
#pragma unroll
        for (int p = 0; p < 5; p++) acc[r][p] = 0ull;

    auto chan_ptr = [&](int ci) -> const float* {
        if (MODE == 0) return (ci < CH) ? A + (size_t)(b * CH + ci) * HW
                                        : Bp + (size_t)(b * CH + (ci - CH)) * HW;
        else if (MODE == 1) return g_fin + (size_t)(b * 2 * CH + ci) * HW;
        else return g_h + (size_t)(b * CH + ci) * HW;
    };

    auto stage = [&](int ck, int buf) {
        const int ci0 = ck * CC;
        const float* wsrc = wT + (size_t)(ci0 * 9) * WCOLS + co_base;
        for (int idx = tid; idx < NW16; idx += 256) {
            int s = idx / (CO_TILE / 4), j = idx % (CO_TILE / 4);
            cp16(swb + (u32)(buf * SM_WF + s * CO_PAD + j * 4) * 4u,
                 wsrc + (size_t)s * WCOLS + j * 4);
        }
        for (int idx = tid; idx < CC * 3 * XW; idx += 256) {
            int ci  = idx / (3 * XW);
            int rem = idx % (3 * XW);
            int ry  = rem / XW;
            int xx  = rem % XW;
            int gx  = xx - 1;
            int gy0 = y0 - 1 + ry;
            int gy1 = gy0 + 1;
            bool okx = (gx >= 0) && (gx < W);
            const float* src = chan_ptr(ci0 + ci) + gy0 * W + gx;
            u32 dst = sib + (u32)(buf * SM_IF + (ci * 3 + ry) * XW + xx) * 8u;
            cp4z(dst,     src,     okx && (gy0 >= 0) && (gy0 < H));
            cp4z(dst + 4, src + W, okx && (gy1 < H));
        }
        cp_commit();
    };

    stage(0, 0);

    for (int ck = 0; ck < NCK; ck++) {
        const int buf = ck & 1;
        if (ck + 1 < NCK) { stage(ck + 1, buf ^ 1); cp_wait1(); }
        else              { cp_wait0(); }
        __syncthreads();

        const float*  wbuf = sW + buf * SM_WF;
        const float2* ibuf = sI + buf * SM_IF;
        for (int ci = 0; ci < CC; ++ci) {
#pragma unroll
            for (int ky = 0; ky < 3; ky++) {
                const ull* ip = reinterpret_cast<const ull*>(&ibuf[(ci * 3 + ky) * XW + x0]);
                ull vv[7];
#pragma unroll
                for (int j = 0; j < 7; j++) vv[j] = ip[j];
#pragma unroll
                for (int kx = 0; kx < 3; kx++) {
                    const int s = ci * KS2 + ky * 3 + kx;
                    const float* wp = &wbuf[s * CO_PAD + tco * RCO];
                    ull w2[RCO];
                    if (RCO == 4) {
                        float4 w4 = *reinterpret_cast<const float4*>(wp);
                        w2[0] = dup2(w4.x); w2[1] = dup2(w4.y);
                        w2[2] = dup2(w4.z); w2[3] = dup2(w4.w);
                    } else {
                        float2 wv = *reinterpret_cast<const float2*>(wp);
                        w2[0] = dup2(wv.x); w2[1] = dup2(wv.y);
                    }
#pragma unroll
                    for (int p = 0; p < 5; p++)
#pragma unroll
                        for (int r = 0; r < RCO; r++) ffma2(acc[r][p], w2[r], vv[kx + p]);
                }
            }
        }
        __syncthreads();
    }

    float* optr = (MODE == 0) ? g_h : (MODE == 3) ? g_off : out_param;
#pragma unroll
    for (int r = 0; r < RCO; r++) {
        int co = co_base + tco * RCO + r;
        if (co >= COUT) continue;
        float bnb, bns = 1.0f, rs = 0.0f;
        if (MODE == 1) {
            float gm = bias_or_bn[co];
            float bt = bias_or_bn[COUT + co];
            float mn = bias_or_bn[2 * COUT + co];
            float vr = bias_or_bn[3 * COUT + co];
            bns = gm * rsqrtf(vr + EPS);
            bnb = bt - mn * bns;
            rs  = *res_scale;
        } else {
            bnb = bias_or_bn[co];
        }
#pragma unroll
        for (int p = 0; p < 5; p++) {
            int x = x0 + p;
            int o0 = ((b * COUT + co) * H + y0) * W + x;
            int o1 = o0 + W;
            float a0, a1;
            unpack2(acc[r][p], a0, a1);
            if (MODE == 0) {
                optr[o0] = silu_(a0 + bnb);
                optr[o1] = silu_(a1 + bnb);
            } else if (MODE == 1) {
                optr[o0] = silu_(a0 * bns + bnb) + rs * g_iral[o0];
                optr[o1] = silu_(a1 * bns + bnb) + rs * g_iral[o1];
            } else {
                optr[o0] = a0 + bnb;
                optr[o1] = a1 + bnb;
            }
        }
    }
}

// fused body+tail kernel for modes 0/1 (688 blocks)
template <int MODE>
__global__ __launch_bounds__(256)
void conv_fused(const float* __restrict__ A, const float* __restrict__ Bp,
                const float* __restrict__ wT,
                const float* __restrict__ bias_or_bn,
                const float* __restrict__ res_scale,
                float* __restrict__ out_param) {
    extern __shared__ float sm[];
    if (blockIdx.x < NA) {
        int t = blockIdx.x;
        conv_body<MODE, 4>(A, Bp, wT, bias_or_bn, res_scale, out_param,
                           sm, t % 320, (t / 320) * 64);
    } else {
        int j = blockIdx.x - NA;
        conv_body<MODE, 2>(A, Bp, wT, bias_or_bn, res_scale, out_param,
                           sm, RP_TAIL + (j >> 1), 64 + 32 * (j & 1));
    }
}

// offset conv (mode 3) — 320 blocks, RCO=2
__global__ __launch_bounds__(256)
void conv_off_kernel(const float* __restrict__ wT,
                     const float* __restrict__ bias) {
    extern __shared__ float sm[];
    conv_body<3, 2>(nullptr, nullptr, wT, bias, nullptr, nullptr,
                    sm, blockIdx.x, 0);
}

// ---------------------------------------------------------------------------
// DCN 1x1 conv body + fused kernel
// ---------------------------------------------------------------------------
constexpr int DCC    = 32;
constexpr int DIELEM = DCC * W;
constexpr int DSM_I  = DCC * W;

template <int RCO>
DEV void dcn_body(const float* __restrict__ bias, float* dsm, int bx, int co_base) {
    constexpr int CO_T   = 16 * RCO;
    constexpr int CO_PAD = CO_T + 4;
    constexpr int DSM_W  = DCC * CO_PAD;
    constexpr int NW16   = DCC * (CO_T / 4);

    float*  sW = dsm;
    float2* sI = (float2*)(dsm + 2 * DSM_W);

    const int tid = threadIdx.x;
    const int tco = tid & 15;
    const int tpx = tid >> 4;
    const int x0  = tpx * 5;
    const int b  = bx / (H / 2);
    const int y0 = (bx % (H / 2)) * 2;

    const u32 swb = smem_u32(sW);
    const u32 sib = smem_u32(sI);
    const float* vbase = g_vals + (size_t)b * KD * HW + (size_t)y0 * W;

    ull acc[RCO][5];
#pragma unroll
    for (int r = 0; r < RCO; r++)
#pragma unroll
        for (int p = 0; p < 5; p++) acc[r][p] = 0ull;

    auto stage = [&](int ck, int buf) {
        const int ci0 = ck * DCC;
        const float* wsrc = g_wdt + (size_t)ci0 * CH + co_base;
        for (int idx = tid; idx < NW16; idx += 256) {
            int s = idx / (CO_T / 4), j = idx % (CO_T / 4);
            cp16(swb + (u32)(buf * DSM_W + s * CO_PAD + j * 4) * 4u,
                 wsrc + (size_t)s * CH + j * 4);
        }
        for (int idx = tid; idx < DIELEM; idx += 256) {
            int ci = idx / W, xx = idx % W;
            const float* src = vbase + (size_t)(ci0 + ci) * HW + xx;
            u32 dst = sib + (u32)(buf * DSM_I + ci * W + xx) * 8u;
            cp4(dst, src);
            cp4(dst + 4, src + W);
        }
        cp_commit();
    };

    stage(0, 0);

    constexpr int NCK = KD / DCC;
    for (int ck = 0; ck < NCK; ck++) {
        const int buf = ck & 1;
        if (ck + 1 < NCK) { stage(ck + 1, buf ^ 1); cp_wait1(); }
        else              { cp_wait0(); }
        __syncthreads();

        const float*  wbuf = sW + buf * DSM_W;
        const float2* ibuf = sI + buf * DSM_I;
#pragma unroll 4
        for (int ci = 0; ci < DCC; ++ci) {
            const ull* ip = reinterpret_cast<const ull*>(&ibuf[ci * W + x0]);
            ull vv[5];
#pragma unroll
            for (int p = 0; p < 5; p++) vv[p] = ip[p];
            ull w2[RCO];
            if (RCO == 4) {
                float4 w4 = *reinterpret_cast<const float4*>(&wbuf[ci * CO_PAD + tco * 4]);
                w2[0] = dup2(w4.x); w2[1] = dup2(w4.y);
                w2[2] = dup2(w4.z); w2[3] = dup2(w4.w);
            } else {
                float2 wv = *reinterpret_cast<const float2*>(&wbuf[ci * CO_PAD + tco * 2]);
                w2[0] = dup2(wv.x); w2[1] = dup2(wv.y);
            }
#pragma unroll
            for (int p = 0; p < 5; p++)
#pragma unroll
                for (int r = 0; r < RCO; r++) ffma2(acc[r][p], w2[r], vv[p]);
        }
        __syncthreads();
    }

#pragma unroll
    for (int r = 0; r < RCO; r++) {
        int co = co_base + tco * RCO + r;
        float bs = __ldg(&bias[co]);
#pragma unroll
        for (int p = 0; p < 5; p++) {
            int x = x0 + p;
            int o0 = ((b * CH + co) * H + y0) * W + x;
            float a0, a1;
            unpack2(acc[r][p], a0, a1);
            g_iral[o0]     = a0 + bs;
            g_iral[o0 + W] = a1 + bs;
        }
    }
}

__global__ __launch_bounds__(256)
void dcn_fused(const float* __restrict__ bias) {
    extern __shared__ float dsm[];
    if (blockIdx.x < NA) {
        int t = blockIdx.x;
        dcn_body<4>(bias, dsm, t % 320, (t / 320) * 64);
    } else {
        int j = blockIdx.x - NA;
        dcn_body<2>(bias, dsm, RP_TAIL + (j >> 1), 64 + 32 * (j & 1));
    }
}

// ---------------------------------------------------------------------------
// Deformable bilinear sampling -> g_vals[b][c*9+k][y][x]
// ---------------------------------------------------------------------------
__global__ __launch_bounds__(256)
void deform_kernel(const float* __restrict__ ir) {
    const int blk   = blockIdx.x;
    const int ytile = blk % 27;
    const int bk    = blk / 27;
    const int k     = bk % 9;
    const int b     = bk / 9;
    const int tid   = threadIdx.x;
    if (tid >= 240) return;
    const int y = ytile * 3 + tid / 80;
    const int x = tid % 80;
    if (y >= H) return;

    const float* obase = g_off + (b * 27) * HW + y * W + x;
    float oy = obase[(2 * k) * HW];
    float ox = obase[(2 * k + 1) * HW];
    float m  = sigm_(obase[(18 + k) * HW]);

    const int ky = k / 3 - 1;
    const int kx = k % 3 - 1;
    float ys = oy + (float)(ky + y);
    float xs = ox + (float)(kx + x);
    float fy = floorf(ys), fx = floorf(xs);
    float wy = ys - fy,    wx = xs - fx;
    int y0 = (int)fy, x0 = (int)fx;
    int y1 = y0 + 1,  x1 = x0 + 1;
    bool vy0 = (y0 >= 0) && (y0 < H);
    bool vy1 = (y1 >= 0) && (y1 < H);
    bool vx0 = (x0 >= 0) && (x0 < W);
    bool vx1 = (x1 >= 0) && (x1 < W);
    float w00 = (1.0f - wy) * (1.0f - wx) * m * ((vy0 && vx0) ? 1.0f : 0.0f);
    float w01 = (1.0f - wy) * wx          * m * ((vy0 && vx1) ? 1.0f : 0.0f);
    float w10 = wy          * (1.0f - wx) * m * ((vy1 && vx0) ? 1.0f : 0.0f);
    float w11 = wy          * wx          * m * ((vy1 && vx1) ? 1.0f : 0.0f);
    int cy0 = min(max(y0, 0), H - 1), cy1 = min(max(y1, 0), H - 1);
    int cx0 = min(max(x0, 0), W - 1), cx1 = min(max(x1, 0), W - 1);
    int i00 = cy0 * W + cx0, i01 = cy0 * W + cx1;
    int i10 = cy1 * W + cx0, i11 = cy1 * W + cx1;

    const float* ib = ir + b * CH * HW;
    float* vout = g_vals + ((size_t)b * CH * 9 + k) * HW + y * W + x;
#pragma unroll 4
    for (int c = 0; c < CH; c++) {
        const float* p = ib + c * HW;
        float v = w00 * __ldg(p + i00) + w01 * __ldg(p + i01)
                + w10 * __ldg(p + i10) + w11 * __ldg(p + i11);
        vout[(size_t)c * 9 * HW] = v;
    }
}

// ---------------------------------------------------------------------------
// Gate stage 1
// ---------------------------------------------------------------------------
__global__ __launch_bounds__(256)
void gate1_kernel(const float* __restrict__ rgb,
                  const float* __restrict__ wg1,
                  const float* __restrict__ bng1) {
    __shared__ float sg[2 * CH * MID];
    const int tid = threadIdx.x;
    for (int i = tid; i < 2 * CH * MID; i += 256) {
        int ci = i >> 4, o = i & 15;
        sg[i] = wg1[o * (2 * CH) + ci];
    }
    __syncthreads();
    const int idx = blockIdx.x * 256 + tid;
    if (idx >= Bn * HW) return;
    const int b = idx / HW, p = idx % HW;

    float acc[MID];
#pragma unroll
    for (int o = 0; o < MID; o++) acc[o] = 0.0f;

    const float* rp = rgb    + b * CH * HW + p;
    const float* ip = g_iral + b * CH * HW + p;
    for (int ci = 0; ci < CH; ci++) {
        float v = rp[ci * HW];
        const float* w = &sg[ci * MID];
#pragma unroll
        for (int o = 0; o < MID; o++) acc[o] += w[o] * v;
    }
    for (int ci = 0; ci < CH; ci++) {
        float v = ip[ci * HW];
        const float* w = &sg[(CH + ci) * MID];
#pragma unroll
        for (int o = 0; o < MID; o++) acc[o] += w[o] * v;
    }
#pragma unroll
    for (int o = 0; o < MID; o++) {
        float gm = bng1[o], bt = bng1[MID + o];
        float mn = bng1[2 * MID + o], vr = bng1[3 * MID + o];
        float sc = gm * rsqrtf(vr + EPS);
        g_g1[(b * MID + o) * HW + p] = silu_(acc[o] * sc + bt - mn * sc);
    }
}

// ---------------------------------------------------------------------------
// Gate stages 2+3, then materialize fused conv input g_fin
// ---------------------------------------------------------------------------
__global__ __launch_bounds__(256)
void gate23_kernel(const float* __restrict__ wg2,
                   const float* __restrict__ bng2,
                   const float* __restrict__ wg3,
                   const float* __restrict__ bg3,
                   const float* __restrict__ rgb) {
    const int idx = blockIdx.x * 256 + threadIdx.x;
    if (idx >= Bn * HW) return;
    const int b = idx / HW, p = idx % HW;
    const int y = p / W, x = p % W;

    float s3 = __ldg(bg3);
#pragma unroll
    for (int o = 0; o < MID; o++) {
        const float* gp = g_g1 + (b * MID + o) * HW;
        float s = 0.0f;
#pragma unroll
        for (int ky = 0; ky < 3; ky++) {
            int yy = y + ky - 1;
            if (yy < 0 || yy >= H) continue;
#pragma unroll
            for (int kx = 0; kx < 3; kx++) {
                int xx = x + kx - 1;
                if (xx < 0 || xx >= W) continue;
                s += gp[yy * W + xx] * __ldg(&wg2[o * 9 + ky * 3 + kx]);
            }
        }
        float gm = __ldg(&bng2[o]), bt = __ldg(&bng2[MID + o]);
        float mn = __ldg(&bng2[2 * MID + o]), vr = __ldg(&bng2[3 * MID + o]);
        float sc = gm * rsqrtf(vr + EPS);
        s3 += silu_(s * sc + bt - mn * sc) * __ldg(&wg3[o]);
    }
    float gv = sigm_(s3);
    g_gate[b * HW + p] = gv;

    const float* ip = g_iral + (size_t)b * CH * HW + p;
    const float* rp = rgb    + (size_t)b * CH * HW + p;
    float* f0 = g_fin + (size_t)b * 2 * CH * HW + p;
    float* f1 = f0 + (size_t)CH * HW;
    float om = 1.0f - gv;
#pragma unroll 4
    for (int c = 0; c < CH; c++) {
        f0[(size_t)c * HW] = gv * ip[(size_t)c * HW];
        f1[(size_t)c * HW] = om * rp[(size_t)c * HW];
    }
}

// ---------------------------------------------------------------------------
// Launcher
// ---------------------------------------------------------------------------
extern "C" void kernel_launch(void* const* d_in, const int* in_sizes, int n_in,
                              void* d_out, int out_size) {
    const float* rgb    = (const float*)d_in[0];
    const float* ir     = (const float*)d_in[1];
    const float* w_off1 = (const float*)d_in[2];
    const float* b_off1 = (const float*)d_in[3];
    const float* w_off2 = (const float*)d_in[4];
    const float* b_off2 = (const float*)d_in[5];
    const float* w_dcn  = (const float*)d_in[6];
    const float* b_dcn  = (const float*)d_in[7];
    const float* w_g1   = (const float*)d_in[8];
    const float* bn_g1  = (const float*)d_in[9];
    const float* w_g2   = (const float*)d_in[10];
    const float* bn_g2  = (const float*)d_in[11];
    const float* w_g3   = (const float*)d_in[12];
    const float* b_g3   = (const float*)d_in[13];
    const float* w_f    = (const float*)d_in[14];
    const float* bn_f   = (const float*)d_in[15];
    const float* rscale = (const float*)d_in[16];
    float* out = (float*)d_out;

    float* w0t; cudaGetSymbolAddress((void**)&w0t, g_w0t);
    float* wft; cudaGetSymbolAddress((void**)&wft, g_wft);
    float* wdt; cudaGetSymbolAddress((void**)&wdt, g_wdt);
    float* w2t; cudaGetSymbolAddress((void**)&w2t, g_w2t);

    // smem sizes sized for the RCO=4 layout (tail path fits inside)
    const int sm_big4 = 2 * ((72 * 68) * 4 + (8 * 3 * 82) * 8);   // 70656 B
    const int sm_big2 = 2 * ((72 * 36) * 4 + (8 * 3 * 82) * 8);   // 52224 B
    const int sm_dcn4 = 2 * ((DCC * 68) * 4 + DSM_I * 8);         // 58368 B

    cudaFuncSetAttribute(conv_fused<0>,  cudaFuncAttributeMaxDynamicSharedMemorySize, sm_big4);
    cudaFuncSetAttribute(conv_fused<1>,  cudaFuncAttributeMaxDynamicSharedMemorySize, sm_big4);
    cudaFuncSetAttribute(conv_off_kernel, cudaFuncAttributeMaxDynamicSharedMemorySize, sm_big2);
    cudaFuncSetAttribute(dcn_fused,      cudaFuncAttributeMaxDynamicSharedMemorySize, sm_dcn4);

    // 0) weight transposes
    prep_w_kernel<<<(2304 * 128 + 255) / 256, 256>>>(w_off1, w0t, 2304, 128, 128);
    prep_w_kernel<<<(2304 * 128 + 255) / 256, 256>>>(w_f,    wft, 2304, 128, 128);
    prep_w_kernel<<<(1152 * 128 + 255) / 256, 256>>>(w_dcn,  wdt, 1152, 128, 128);
    prep_w_kernel<<<(1152 * 32 + 255) / 256, 256>>>(w_off2,  w2t, 1152, 32, 27);

    // 1) h = silu(conv3x3(concat(rgb, ir)))  — fused body+tail, 688 blocks
    conv_fused<0><<<NBLK, 256, sm_big4>>>(rgb, ir, w0t, b_off1, nullptr, nullptr);
    // 2) offset/mask conv (27 ch)
    conv_off_kernel<<<320, 256, sm_big2>>>(w2t, b_off2);
    // 3) deformable bilinear sampling * mask -> g_vals
    deform_kernel<<<Bn * 9 * 27, 256>>>(ir);
    // 4) ir_aligned = vals . w_dcn + b_dcn — fused body+tail
    dcn_fused<<<NBLK, 256, sm_dcn4>>>(b_dcn);
    // 5) gate stage 1
    gate1_kernel<<<(Bn * HW + 255) / 256, 256>>>(rgb, w_g1, bn_g1);
    // 6) gate stages 2+3 + fused-input materialization
    gate23_kernel<<<(Bn * HW + 255) / 256, 256>>>(w_g2, bn_g2, w_g3, b_g3, rgb);
    // 7) fused conv + BN + SiLU + residual -> out — fused body+tail
    conv_fused<1><<<NBLK, 256, sm_big4>>>(nullptr, nullptr, wft, bn_f, rscale, out);
}

// round 14
// speedup vs baseline: 1.9146x; 1.0138x over previous
#include <cuda_runtime.h>

// ---------------------------------------------------------------------------
// Problem constants
// ---------------------------------------------------------------------------
constexpr int Bn  = 8;
constexpr int CH  = 128;
constexpr int H   = 80;
constexpr int W   = 80;
constexpr int HW  = H * W;
constexpr int MID = 16;
constexpr int KD  = CH * 9;          // 1152
constexpr float EPS = 1e-5f;

// tail-split: 640 tiles = 592 full (2 exact waves at 296 slots) + 48 -> 96 halves
constexpr int NTILE   = 640;
constexpr int NA      = 592;
constexpr int NBLK    = NA + 2 * (NTILE - NA);   // 688 blocks per heavy conv
constexpr int RP_TAIL = 272;

// ---------------------------------------------------------------------------
// Scratch
// ---------------------------------------------------------------------------
__device__ float g_h[Bn * CH * HW];
__device__ float g_off[Bn * 27 * HW];            // CIN half 0 partial
__device__ float g_off2[Bn * 27 * HW];           // CIN half 1 partial
__device__ float g_vals[(size_t)Bn * CH * 9 * HW];
__device__ float g_iral[Bn * CH * HW];
__device__ float g_g1[Bn * MID * HW];
__device__ float g_gate[Bn * HW];
__device__ float g_fin[Bn * 2 * CH * HW];
// transposed weights [k][co]
__device__ float g_w0t[2 * CH * 9 * CH];
__device__ float g_wft[2 * CH * 9 * CH];
__device__ float g_wdt[KD * CH];
__device__ float g_w2t[KD * 32];

#define DEV __device__ __forceinline__
typedef unsigned long long ull;
typedef unsigned int u32;

DEV float sigm_(float x) { return 1.0f / (1.0f + __expf(-x)); }
DEV float silu_(float x) { return x * sigm_(x); }

DEV void ffma2(ull& d, ull a, ull b) {
    asm("fma.rn.f32x2 %0, %1, %2, %0;" : "+l"(d) : "l"(a), "l"(b));
}
DEV ull dup2(float w) { ull u; asm("mov.b64 %0, {%1, %1};" : "=l"(u) : "f"(w)); return u; }
DEV void unpack2(ull u, float& x, float& y) {
    asm("mov.b64 {%0, %1}, %2;" : "=f"(x), "=f"(y) : "l"(u));
}
DEV u32 smem_u32(const void* p) {
    u32 a; asm("{ .reg .u64 t; cvta.to.shared.u64 t, %1; cvt.u32.u64 %0, t; }" : "=r"(a) : "l"(p));
    return a;
}
DEV void cp4(u32 dst, const float* src) {
    asm volatile("cp.async.ca.shared.global [%0], [%1], 4;" :: "r"(dst), "l"(src) : "memory");
}
DEV void cp16(u32 dst, const float* src) {
    asm volatile("cp.async.cg.shared.global [%0], [%1], 16;" :: "r"(dst), "l"(src) : "memory");
}
DEV void cp4z(u32 dst, const float* src, bool ok) {
    int sz = ok ? 4 : 0;
    asm volatile("cp.async.ca.shared.global [%0], [%1], 4, %2;"
                 :: "r"(dst), "l"(src), "r"(sz) : "memory");
}
DEV void cp_commit() { asm volatile("cp.async.commit_group;" ::: "memory"); }
DEV void cp_wait1()  { asm volatile("cp.async.wait_group 1;" ::: "memory"); }
DEV void cp_wait0()  { asm volatile("cp.async.wait_group 0;" ::: "memory"); }

// ---------------------------------------------------------------------------
// Merged weight transpose prep (all 4 tensors in one launch)
// segments: w_off1 -> g_w0t (2304x128), w_f -> g_wft (2304x128),
//           w_dcn -> g_wdt (1152x128), w_off2 -> g_w2t (1152x32, 27 padded)
// ---------------------------------------------------------------------------
constexpr int PW_N0 = 2304 * 128;
constexpr int PW_N1 = PW_N0 + 2304 * 128;
constexpr int PW_N2 = PW_N1 + 1152 * 128;
constexpr int PW_N3 = PW_N2 + 1152 * 32;

__global__ __launch_bounds__(256)
void prep_all_kernel(const float* __restrict__ w_off1, const float* __restrict__ w_f,
                     const float* __restrict__ w_dcn,  const float* __restrict__ w_off2) {
    int idx = blockIdx.x * 256 + threadIdx.x;
    if (idx >= PW_N3) return;
    const float* src; float* dst; int K, cols, cout, base;
    if (idx < PW_N0)      { src = w_off1; dst = g_w0t; K = 2304; cols = 128; cout = 128; base = 0; }
    else if (idx < PW_N1) { src = w_f;    dst = g_wft; K = 2304; cols = 128; cout = 128; base = PW_N0; }
    else if (idx < PW_N2) { src = w_dcn;  dst = g_wdt; K = 1152; cols = 128; cout = 128; base = PW_N1; }
    else                  { src = w_off2; dst = g_w2t; K = 1152; cols = 32;  cout = 27;  base = PW_N2; }
    int i = idx - base;
    int r = i / cols, co = i % cols;
    dst[i] = (co < cout) ? src[(size_t)co * K + r] : 0.0f;
}

// ---------------------------------------------------------------------------
// 3x3 conv body (device function), cp.async double-buffered.
//   MODE 0: concat(rgb, ir)  Cin=256 -> g_h   (silu(v+b))
//   MODE 1: g_fin            Cin=256 -> out   (silu(bn)+res)
//   MODE 3: g_h half-CIN     Cin=64  -> g_off/g_off2 (raw partial, no bias)
// ---------------------------------------------------------------------------
template <int MODE, int RCO>
DEV void conv_body(const float* __restrict__ A, const float* __restrict__ Bp,
                   const float* __restrict__ wT,
                   const float* __restrict__ bias_or_bn,
                   const float* __restrict__ res_scale,
                   float* __restrict__ out_param,
                   float* sm, int bx, int co_base, int ci_base) {
    constexpr int KS2  = 9;
    constexpr int CINL = (MODE == 3) ? (CH / 2) : 2 * CH;   // channels this block
    constexpr int COUT = (MODE == 3) ? 27 : CH;
    constexpr int CO_TILE = 16 * RCO;
    constexpr int CO_PAD  = CO_TILE + 4;
    constexpr int WCOLS = (MODE == 3) ? 32 : 128;
    constexpr int CC   = 8;
    constexpr int S    = CC * KS2;                  // 72
    constexpr int XW   = W + 2;
    constexpr int SM_WF = S * CO_PAD;
    constexpr int SM_IF = CC * 3 * XW;
    constexpr int NCK  = CINL / CC;
    constexpr int NW16 = S * (CO_TILE / 4);

    float*  sW = sm;                               // [2][SM_WF]
    float2* sI = (float2*)(sm + 2 * SM_WF);        // [2][SM_IF]

    const int tid = threadIdx.x;
    const int tco = tid & 15;
    const int tpx = tid >> 4;
    const int x0  = tpx * 5;
    const int b  = bx / (H / 2);
    const int y0 = (bx % (H / 2)) * 2;

    const u32 swb = smem_u32(sW);
    const u32 sib = smem_u32(sI);

    ull acc[RCO][5];
#pragma unroll
    for (int r = 0; r < RCO; r++)
#pragma unroll
        for (int p = 0; p < 5; p++) acc[r][p] = 0ull;

    auto chan_ptr = [&](int ci) -> const float* {
        if (MODE == 0) return (ci < CH) ? A + (size_t)(b * CH + ci) * HW
                                        : Bp + (size_t)(b * CH + (ci - CH)) * HW;
        else if (MODE == 1) return g_fin + (size_t)(b * 2 * CH + ci) * HW;
        else return g_h + (size_t)(b * CH + ci) * HW;
    };

    auto stage = [&](int ck, int buf) {
        const int ci0 = ci_base + ck * CC;
        const float* wsrc = wT + (size_t)(ci0 * 9) * WCOLS + co_base;
        for (int idx = tid; idx < NW16; idx += 256) {
            int s = idx / (CO_TILE / 4), j = idx % (CO_TILE / 4);
            cp16(swb + (u32)(buf * SM_WF + s * CO_PAD + j * 4) * 4u,
                 wsrc + (size_t)s * WCOLS + j * 4);
        }
        for (int idx = tid; idx < CC * 3 * XW; idx += 256) {
            int ci  = idx / (3 * XW);
            int rem = idx % (3 * XW);
            int ry  = rem / XW;
            int xx  = rem % XW;
            int gx  = xx - 1;
            int gy0 = y0 - 1 + ry;
            int gy1 = gy0 + 1;
            bool okx = (gx >= 0) && (gx < W);
            const float* src = chan_ptr(ci0 + ci) + gy0 * W + gx;
            u32 dst = sib + (u32)(buf * SM_IF + (ci * 3 + ry) * XW + xx) * 8u;
            cp4z(dst,     src,     okx && (gy0 >= 0) && (gy0 < H));
            cp4z(dst + 4, src + W, okx && (gy1 < H));
        }
        cp_commit();
    };

    stage(0, 0);

    for (int ck = 0; ck < NCK; ck++) {
        const int buf = ck & 1;
        if (ck + 1 < NCK) { stage(ck + 1, buf ^ 1); cp_wait1(); }
        else              { cp_wait0(); }
        __syncthreads();

        const float*  wbuf = sW + buf * SM_WF;
        const float2* ibuf = sI + buf * SM_IF;
        for (int ci = 0; ci < CC; ++ci) {
#pragma unroll
            for (int ky = 0; ky < 3; ky++) {
                const ull* ip = reinterpret_cast<const ull*>(&ibuf[(ci * 3 + ky) * XW + x0]);
                ull vv[7];
#pragma unroll
                for (int j = 0; j < 7; j++) vv[j] = ip[j];
#pragma unroll
                for (int kx = 0; kx < 3; kx++) {
                    const int s = ci * KS2 + ky * 3 + kx;
                    const float* wp = &wbuf[s * CO_PAD + tco * RCO];
                    ull w2[RCO];
                    if (RCO == 4) {
                        float4 w4 = *reinterpret_cast<const float4*>(wp);
                        w2[0] = dup2(w4.x); w2[1] = dup2(w4.y);
                        w2[2] = dup2(w4.z); w2[3] = dup2(w4.w);
                    } else {
                        float2 wv = *reinterpret_cast<const float2*>(wp);
                        w2[0] = dup2(wv.x); w2[1] = dup2(wv.y);
                    }
#pragma unroll
                    for (int p = 0; p < 5; p++)
#pragma unroll
                        for (int r = 0; r < RCO; r++) ffma2(acc[r][p], w2[r], vv[kx + p]);
                }
            }
        }
        __syncthreads();
    }

    float* optr = (MODE == 0) ? g_h : (MODE == 3) ? out_param : out_param;
#pragma unroll
    for (int r = 0; r < RCO; r++) {
        int co = co_base + tco * RCO + r;
        if (co >= COUT) continue;
        float bnb = 0.0f, bns = 1.0f, rs = 0.0f;
        if (MODE == 1) {
            float gm = bias_or_bn[co];
            float bt = bias_or_bn[COUT + co];
            float mn = bias_or_bn[2 * COUT + co];
            float vr = bias_or_bn[3 * COUT + co];
            bns = gm * rsqrtf(vr + EPS);
            bnb = bt - mn * bns;
            rs  = *res_scale;
        } else if (MODE == 0) {
            bnb = bias_or_bn[co];
        }
#pragma unroll
        for (int p = 0; p < 5; p++) {
            int x = x0 + p;
            int o0 = ((b * COUT + co) * H + y0) * W + x;
            int o1 = o0 + W;
            float a0, a1;
            unpack2(acc[r][p], a0, a1);
            if (MODE == 0) {
                optr[o0] = silu_(a0 + bnb);
                optr[o1] = silu_(a1 + bnb);
            } else if (MODE == 1) {
                optr[o0] = silu_(a0 * bns + bnb) + rs * g_iral[o0];
                optr[o1] = silu_(a1 * bns + bnb) + rs * g_iral[o1];
            } else {
                optr[o0] = a0;     // raw partial; bias added in deform
                optr[o1] = a1;
            }
        }
    }
}

// fused body+tail kernel for modes 0/1 (688 blocks)
template <int MODE>
__global__ __launch_bounds__(256)
void conv_fused(const float* __restrict__ A, const float* __restrict__ Bp,
                const float* __restrict__ wT,
                const float* __restrict__ bias_or_bn,
                const float* __restrict__ res_scale,
                float* __restrict__ out_param) {
    extern __shared__ float sm[];
    if (blockIdx.x < NA) {
        int t = blockIdx.x;
        conv_body<MODE, 4>(A, Bp, wT, bias_or_bn, res_scale, out_param,
                           sm, t % 320, (t / 320) * 64, 0);
    } else {
        int j = blockIdx.x - NA;
        conv_body<MODE, 2>(A, Bp, wT, bias_or_bn, res_scale, out_param,
                           sm, RP_TAIL + (j >> 1), 64 + 32 * (j & 1), 0);
    }
}

// offset conv (mode 3) — 640 blocks: 320 row-pairs x 2 CIN-halves
__global__ __launch_bounds__(256)
void conv_off_kernel(const float* __restrict__ wT) {
    extern __shared__ float sm[];
    const int half = blockIdx.x >= 320;
    const int bx   = blockIdx.x - (half ? 320 : 0);
    conv_body<3, 2>(nullptr, nullptr, wT, nullptr, nullptr,
                    half ? g_off2 : g_off, sm, bx, 0, half ? (CH / 2) : 0);
}

// ---------------------------------------------------------------------------
// DCN 1x1 conv body + fused kernel
// ---------------------------------------------------------------------------
constexpr int DCC    = 32;
constexpr int DIELEM = DCC * W;
constexpr int DSM_I  = DCC * W;

template <int RCO>
DEV void dcn_body(const float* __restrict__ bias, float* dsm, int bx, int co_base) {
    constexpr int CO_T   = 16 * RCO;
    constexpr int CO_PAD = CO_T + 4;
    constexpr int DSM_W  = DCC * CO_PAD;
    constexpr int NW16   = DCC * (CO_T / 4);

    float*  sW = dsm;
    float2* sI = (float2*)(dsm + 2 * DSM_W);

    const int tid = threadIdx.x;
    const int tco = tid & 15;
    const int tpx = tid >> 4;
    const int x0  = tpx * 5;
    const int b  = bx / (H / 2);
    const int y0 = (bx % (H / 2)) * 2;

    const u32 swb = smem_u32(sW);
    const u32 sib = smem_u32(sI);
    const float* vbase = g_vals + (size_t)b * KD * HW + (size_t)y0 * W;

    ull acc[RCO][5];
#pragma unroll
    for (int r = 0; r < RCO; r++)
#pragma unroll
        for (int p = 0; p < 5; p++) acc[r][p] = 0ull;

    auto stage = [&](int ck, int buf) {
        const int ci0 = ck * DCC;
        const float* wsrc = g_wdt + (size_t)ci0 * CH + co_base;
        for (int idx = tid; idx < NW16; idx += 256) {
            int s = idx / (CO_T / 4), j = idx % (CO_T / 4);
            cp16(swb + (u32)(buf * DSM_W + s * CO_PAD + j * 4) * 4u,
                 wsrc + (size_t)s * CH + j * 4);
        }
        for (int idx = tid; idx < DIELEM; idx += 256) {
            int ci = idx / W, xx = idx % W;
            const float* src = vbase + (size_t)(ci0 + ci) * HW + xx;
            u32 dst = sib + (u32)(buf * DSM_I + ci * W + xx) * 8u;
            cp4(dst, src);
            cp4(dst + 4, src + W);
        }
        cp_commit();
    };

    stage(0, 0);

    constexpr int NCK = KD / DCC;
    for (int ck = 0; ck < NCK; ck++) {
        const int buf = ck & 1;
        if (ck + 1 < NCK) { stage(ck + 1, buf ^ 1); cp_wait1(); }
        else              { cp_wait0(); }
        __syncthreads();

        const float*  wbuf = sW + buf * DSM_W;
        const float2* ibuf = sI + buf * DSM_I;
#pragma unroll 4
        for (int ci = 0; ci < DCC; ++ci) {
            const ull* ip = reinterpret_cast<const ull*>(&ibuf[ci * W + x0]);
            ull vv[5];
#pragma unroll
            for (int p = 0; p < 5; p++) vv[p] = ip[p];
            ull w2[RCO];
            if (RCO == 4) {
                float4 w4 = *reinterpret_cast<const float4*>(&wbuf[ci * CO_PAD + tco * 4]);
                w2[0] = dup2(w4.x); w2[1] = dup2(w4.y);
                w2[2] = dup2(w4.z); w2[3] = dup2(w4.w);
            } else {
                float2 wv = *reinterpret_cast<const float2*>(&wbuf[ci * CO_PAD + tco * 2]);
                w2[0] = dup2(wv.x); w2[1] = dup2(wv.y);
            }
#pragma unroll
            for (int p = 0; p < 5; p++)
#pragma unroll
                for (int r = 0; r < RCO; r++) ffma2(acc[r][p], w2[r], vv[p]);
        }
        __syncthreads();
    }

#pragma unroll
    for (int r = 0; r < RCO; r++) {
        int co = co_base + tco * RCO + r;
        float bs = __ldg(&bias[co]);
#pragma unroll
        for (int p = 0; p < 5; p++) {
            int x = x0 + p;
            int o0 = ((b * CH + co) * H + y0) * W + x;
            float a0, a1;
            unpack2(acc[r][p], a0, a1);
            g_iral[o0]     = a0 + bs;
            g_iral[o0 + W] = a1 + bs;
        }
    }
}

__global__ __launch_bounds__(256)
void dcn_fused(const float* __restrict__ bias) {
    extern __shared__ float dsm[];
    if (blockIdx.x < NA) {
        int t = blockIdx.x;
        dcn_body<4>(bias, dsm, t % 320, (t / 320) * 64);
    } else {
        int j = blockIdx.x - NA;
        dcn_body<2>(bias, dsm, RP_TAIL + (j >> 1), 64 + 32 * (j & 1));
    }
}

// ---------------------------------------------------------------------------
// Deformable bilinear sampling -> g_vals[b][c*9+k][y][x]
// offset = g_off + g_off2 + bias (conv3 partials summed here)
// ---------------------------------------------------------------------------
__global__ __launch_bounds__(256)
void deform_kernel(const float* __restrict__ ir, const float* __restrict__ boff) {
    const int blk   = blockIdx.x;
    const int ytile = blk % 27;
    const int bk    = blk / 27;
    const int k     = bk % 9;
    const int b     = bk / 9;
    const int tid   = threadIdx.x;
    if (tid >= 240) return;
    const int y = ytile * 3 + tid / 80;
    const int x = tid % 80;
    if (y >= H) return;

    const int pidx = (b * 27) * HW + y * W + x;
    const float* o1p = g_off  + pidx;
    const float* o2p = g_off2 + pidx;
    float oy = o1p[(2 * k) * HW]     + o2p[(2 * k) * HW]     + __ldg(&boff[2 * k]);
    float ox = o1p[(2 * k + 1) * HW] + o2p[(2 * k + 1) * HW] + __ldg(&boff[2 * k + 1]);
    float m  = sigm_(o1p[(18 + k) * HW] + o2p[(18 + k) * HW] + __ldg(&boff[18 + k]));

    const int ky = k / 3 - 1;
    const int kx = k % 3 - 1;
    float ys = oy + (float)(ky + y);
    float xs = ox + (float)(kx + x);
    float fy = floorf(ys), fx = floorf(xs);
    float wy = ys - fy,    wx = xs - fx;
    int y0 = (int)fy, x0 = (int)fx;
    int y1 = y0 + 1,  x1 = x0 + 1;
    bool vy0 = (y0 >= 0) && (y0 < H);
    bool vy1 = (y1 >= 0) && (y1 < H);
    bool vx0 = (x0 >= 0) && (x0 < W);
    bool vx1 = (x1 >= 0) && (x1 < W);
    float w00 = (1.0f - wy) * (1.0f - wx) * m * ((vy0 && vx0) ? 1.0f : 0.0f);
    float w01 = (1.0f - wy) * wx          * m * ((vy0 && vx1) ? 1.0f : 0.0f);
    float w10 = wy          * (1.0f - wx) * m * ((vy1 && vx0) ? 1.0f : 0.0f);
    float w11 = wy          * wx          * m * ((vy1 && vx1) ? 1.0f : 0.0f);
    int cy0 = min(max(y0, 0), H - 1), cy1 = min(max(y1, 0), H - 1);
    int cx0 = min(max(x0, 0), W - 1), cx1 = min(max(x1, 0), W - 1);
    int i00 = cy0 * W + cx0, i01 = cy0 * W + cx1;
    int i10 = cy1 * W + cx0, i11 = cy1 * W + cx1;

    const float* ib = ir + b * CH * HW;
    float* vout = g_vals + ((size_t)b * CH * 9 + k) * HW + y * W + x;
#pragma unroll 4
    for (int c = 0; c < CH; c++) {
        const float* p = ib + c * HW;
        float v = w00 * __ldg(p + i00) + w01 * __ldg(p + i01)
                + w10 * __ldg(p + i10) + w11 * __ldg(p + i11);
        vout[(size_t)c * 9 * HW] = v;
    }
}

// ---------------------------------------------------------------------------
// Gate stage 1
// ---------------------------------------------------------------------------
__global__ __launch_bounds__(256)
void gate1_kernel(const float* __restrict__ rgb,
                  const float* __restrict__ wg1,
                  const float* __restrict__ bng1) {
    __shared__ float sg[2 * CH * MID];
    const int tid = threadIdx.x;
    for (int i = tid; i < 2 * CH * MID; i += 256) {
        int ci = i >> 4, o = i & 15;
        sg[i] = wg1[o * (2 * CH) + ci];
    }
    __syncthreads();
    const int idx = blockIdx.x * 256 + tid;
    if (idx >= Bn * HW) return;
    const int b = idx / HW, p = idx % HW;

    float acc[MID];
#pragma unroll
    for (int o = 0; o < MID; o++) acc[o] = 0.0f;

    const float* rp = rgb    + b * CH * HW + p;
    const float* ip = g_iral + b * CH * HW + p;
    for (int ci = 0; ci < CH; ci++) {
        float v = rp[ci * HW];
        const float* w = &sg[ci * MID];
#pragma unroll
        for (int o = 0; o < MID; o++) acc[o] += w[o] * v;
    }
    for (int ci = 0; ci < CH; ci++) {
        float v = ip[ci * HW];
        const float* w = &sg[(CH + ci) * MID];
#pragma unroll
        for (int o = 0; o < MID; o++) acc[o] += w[o] * v;
    }
#pragma unroll
    for (int o = 0; o < MID; o++) {
        float gm = bng1[o], bt = bng1[MID + o];
        float mn = bng1[2 * MID + o], vr = bng1[3 * MID + o];
        float sc = gm * rsqrtf(vr + EPS);
        g_g1[(b * MID + o) * HW + p] = silu_(acc[o] * sc + bt - mn * sc);
    }
}

// ---------------------------------------------------------------------------
// Gate stages 2+3, then materialize fused conv input g_fin
// ---------------------------------------------------------------------------
__global__ __launch_bounds__(256)
void gate23_kernel(const float* __restrict__ wg2,
                   const float* __restrict__ bng2,
                   const float* __restrict__ wg3,
                   const float* __restrict__ bg3,
                   const float* __restrict__ rgb) {
    const int idx = blockIdx.x * 256 + threadIdx.x;
    if (idx >= Bn * HW) return;
    const int b = idx / HW, p = idx % HW;
    const int y = p / W, x = p % W;

    float s3 = __ldg(bg3);
#pragma unroll
    for (int o = 0; o < MID; o++) {
        const float* gp = g_g1 + (b * MID + o) * HW;
        float s = 0.0f;
#pragma unroll
        for (int ky = 0; ky < 3; ky++) {
            int yy = y + ky - 1;
            if (yy < 0 || yy >= H) continue;
#pragma unroll
            for (int kx = 0; kx < 3; kx++) {
                int xx = x + kx - 1;
                if (xx < 0 || xx >= W) continue;
                s += gp[yy * W + xx] * __ldg(&wg2[o * 9 + ky * 3 + kx]);
            }
        }
        float gm = __ldg(&bng2[o]), bt = __ldg(&bng2[MID + o]);
        float mn = __ldg(&bng2[2 * MID + o]), vr = __ldg(&bng2[3 * MID + o]);
        float sc = gm * rsqrtf(vr + EPS);
        s3 += silu_(s * sc + bt - mn * sc) * __ldg(&wg3[o]);
    }
    float gv = sigm_(s3);
    g_gate[b * HW + p] = gv;

    const float* ip = g_iral + (size_t)b * CH * HW + p;
    const float* rp = rgb    + (size_t)b * CH * HW + p;
    float* f0 = g_fin + (size_t)b * 2 * CH * HW + p;
    float* f1 = f0 + (size_t)CH * HW;
    float om = 1.0f - gv;
#pragma unroll 4
    for (int c = 0; c < CH; c++) {
        f0[(size_t)c * HW] = gv * ip[(size_t)c * HW];
        f1[(size_t)c * HW] = om * rp[(size_t)c * HW];
    }
}

// ---------------------------------------------------------------------------
// Launcher
// ---------------------------------------------------------------------------
extern "C" void kernel_launch(void* const* d_in, const int* in_sizes, int n_in,
                              void* d_out, int out_size) {
    const float* rgb    = (const float*)d_in[0];
    const float* ir     = (const float*)d_in[1];
    const float* w_off1 = (const float*)d_in[2];
    const float* b_off1 = (const float*)d_in[3];
    const float* w_off2 = (const float*)d_in[4];
    const float* b_off2 = (const float*)d_in[5];
    const float* w_dcn  = (const float*)d_in[6];
    const float* b_dcn  = (const float*)d_in[7];
    const float* w_g1   = (const float*)d_in[8];
    const float* bn_g1  = (const float*)d_in[9];
    const float* w_g2   = (const float*)d_in[10];
    const float* bn_g2  = (const float*)d_in[11];
    const float* w_g3   = (const float*)d_in[12];
    const float* b_g3   = (const float*)d_in[13];
    const float* w_f    = (const float*)d_in[14];
    const float* bn_f   = (const float*)d_in[15];
    const float* rscale = (const float*)d_in[16];
    float* out = (float*)d_out;

    float* w0t; cudaGetSymbolAddress((void**)&w0t, g_w0t);
    float* wft; cudaGetSymbolAddress((void**)&wft, g_wft);
    float* w2t; cudaGetSymbolAddress((void**)&w2t, g_w2t);

    const int sm_big4 = 2 * ((72 * 68) * 4 + (8 * 3 * 82) * 8);   // 70656 B
    const int sm_big2 = 2 * ((72 * 36) * 4 + (8 * 3 * 82) * 8);   // 52224 B
    const int sm_dcn4 = 2 * ((DCC * 68) * 4 + DSM_I * 8);         // 58368 B

    cudaFuncSetAttribute(conv_fused<0>,   cudaFuncAttributeMaxDynamicSharedMemorySize, sm_big4);
    cudaFuncSetAttribute(conv_fused<1>,   cudaFuncAttributeMaxDynamicSharedMemorySize, sm_big4);
    cudaFuncSetAttribute(conv_off_kernel, cudaFuncAttributeMaxDynamicSharedMemorySize, sm_big2);
    cudaFuncSetAttribute(dcn_fused,       cudaFuncAttributeMaxDynamicSharedMemorySize, sm_dcn4);

    // 0) merged weight transposes
    prep_all_kernel<<<(PW_N3 + 255) / 256, 256>>>(w_off1, w_f, w_dcn, w_off2);

    // 1) h = silu(conv3x3(concat(rgb, ir)))  — fused body+tail, 688 blocks
    conv_fused<0><<<NBLK, 256, sm_big4>>>(rgb, ir, w0t, b_off1, nullptr, nullptr);
    // 2) offset/mask conv — 640 half-CIN blocks, partial sums
    conv_off_kernel<<<640, 256, sm_big2>>>(w2t);
    // 3) deformable sampling (sums partials + bias) -> g_vals
    deform_kernel<<<Bn * 9 * 27, 256>>>(ir, b_off2);
    // 4) ir_aligned = vals . w_dcn + b_dcn — fused body+tail
    dcn_fused<<<NBLK, 256, sm_dcn4>>>(b_dcn);
    // 5) gate stage 1
    gate1_kernel<<<(Bn * HW + 255) / 256, 256>>>(rgb, w_g1, bn_g1);
    // 6) gate stages 2+3 + fused-input materialization
    gate23_kernel<<<(Bn * HW + 255) / 256, 256>>>(w_g2, bn_g2, w_g3, b_g3, rgb);
    // 7) fused conv + BN + SiLU + residual -> out — fused body+tail
    conv_fused<1><<<NBLK, 256, sm_big4>>>(nullptr, nullptr, wft, bn_f, rscale, out);
}